// round 13
// baseline (speedup 1.0000x reference)
#include <cuda_runtime.h>
#include <cstdint>
#include <math.h>

#define SQ   4096
#define NSEQ 80
#define CH   128
#define CH0  64

// ---------------- device scratch ----------------
__device__ int   g_len[NSEQ];
__device__ float g_x[NSEQ * SQ * 3];
__device__ float g_h0[(size_t)NSEQ * SQ * CH0];
__device__ float g_bufA[(size_t)NSEQ * SQ * CH];
__device__ float g_bufB[(size_t)NSEQ * SQ * CH];
__device__ float g_skip[(size_t)NSEQ * SQ * CH];
__device__ float g_mean0[NSEQ * CH0];
__device__ float g_mean1[NSEQ * CH];
__device__ float g_cv1T[CH0 * CH];       // cv1_w transposed [k][o]
__device__ float g_rwT[3 * CH * CH];     // rs_rw transposed per stack [k][o]
__device__ float g_swT[3 * CH * CH];

__device__ __forceinline__ float sigmoidf_(float x) { return 1.f / (1.f + expf(-x)); }

__device__ __forceinline__ void cpasync16(unsigned saddr, const void* gptr) {
    asm volatile("cp.async.cg.shared.global [%0], [%1], 16;" :: "r"(saddr), "l"(gptr));
}
__device__ __forceinline__ void cpcommit() { asm volatile("cp.async.commit_group;"); }
__device__ __forceinline__ void cpwait0()  { asm volatile("cp.async.wait_group 0;" ::: "memory"); }

// stage chunk c (8 k-rows = 256 float4 per matrix) of two weight matrices into wbuf[buf]
__device__ __forceinline__ void issue_chunk(unsigned wb0, int buf, int t,
                                            const float* fsrc, const float* gsrc, int c) {
    unsigned d = wb0 + (unsigned)buf * 8192u + (unsigned)t * 16u;
    cpasync16(d,         (const float4*)fsrc + c * 256 + t);
    cpasync16(d + 4096u, (const float4*)gsrc + c * 256 + t);
    cpcommit();
}

// ---- packed f32x2 helpers ----
#define PK2(D, LO, HI) \
    asm("mov.b64 %0, {%1, %2};" : "=l"(D) : "f"(LO), "f"(HI))
#define UPK2(LO, HI, S) \
    asm("mov.b64 {%0, %1}, %2;" : "=f"(LO), "=f"(HI) : "l"(S))
#define FMA2(ACC, A, W) \
    asm("fma.rn.f32x2 %0, %1, %2, %0;" : "+l"(ACC) : "l"(A), "l"(W))

// ---------------- 1. stable gather per (batch, class) + zero mean buffers ----------------
__global__ void gather_kernel(const float* __restrict__ raw, const int* __restrict__ labels) {
    int seq = blockIdx.x;
    int b = seq / 10, cls = seq % 10 + 1;
    const int* lab = labels + b * SQ;
    __shared__ int cnt[256];
    __shared__ int scan[257];
    int t = threadIdx.x;
    if (t < CH0) g_mean0[seq * CH0 + t] = 0.f;
    if (t < CH)  g_mean1[seq * CH + t]  = 0.f;
    int base = t * 16;
    int c = 0;
#pragma unroll
    for (int u = 0; u < 16; u++) c += (lab[base + u] == cls);
    cnt[t] = c;
    __syncthreads();
    if (t == 0) {
        int acc = 0;
        for (int i = 0; i < 256; i++) { scan[i] = acc; acc += cnt[i]; }
        scan[256] = acc;
        g_len[seq] = acc;
    }
    __syncthreads();
    int w = scan[t];
    const float* xb = raw + (size_t)b * SQ * 3;
    float* dst = g_x + (size_t)seq * SQ * 3;
    for (int u = 0; u < 16; u++) {
        int s = base + u;
        if (lab[s] == cls) {
            dst[w * 3 + 0] = xb[s * 3 + 0];
            dst[w * 3 + 1] = xb[s * 3 + 1];
            dst[w * 3 + 2] = xb[s * 3 + 2];
            w++;
        }
    }
}

// ---------------- prep: transpose small weight matrices ----------------
__global__ void prep_kernel(const float* __restrict__ cv1_w,
                            const float* __restrict__ rw, const float* __restrict__ sw) {
    int idx = blockIdx.x * 256 + threadIdx.x;
    if (idx < CH0 * CH) {
        int k = idx / CH, o = idx % CH;
        g_cv1T[idx] = cv1_w[o * CH0 + k];
    }
    if (idx < 3 * CH * CH) {
        int st = idx / (CH * CH);
        int r = idx % (CH * CH);
        int k = r / CH, o = r % CH;
        g_rwT[idx] = rw[(size_t)st * CH * CH + o * CH + k];
        g_swT[idx] = sw[(size_t)st * CH * CH + o * CH + k];
    }
}

// ---------------- 2. cv0 (K=3), tile-stride loop, fused SE0 mean partial-sums ----------------
__global__ void cv0_kernel(const float* __restrict__ w, const float* __restrict__ b) {
    int seq = blockIdx.y;
    int L = g_len[seq];
    __shared__ float ws[CH0 * 3];
    __shared__ float bs[CH0];
    __shared__ float msum[CH0];
    int t = threadIdx.x;
    if (t < CH0 * 3) ws[t] = w[t];
    if (t < CH0) { bs[t] = b[t]; msum[t] = 0.f; }
    __syncthreads();
    int c0 = (t & 15) * 4;
    for (int j0 = blockIdx.x * 16; j0 < L; j0 += gridDim.x * 16) {
        int j = j0 + (t >> 4);
        if (j < L) {
            const float* xp = g_x + ((size_t)seq * SQ + j) * 3;
            float x0 = xp[0], x1 = xp[1], x2 = xp[2];
            float* out = g_h0 + ((size_t)seq * SQ + j) * CH0;
            float v0 = fmaxf(fmaf(x0, ws[(c0+0)*3+0], fmaf(x1, ws[(c0+0)*3+1], fmaf(x2, ws[(c0+0)*3+2], bs[c0+0]))), 0.f);
            float v1 = fmaxf(fmaf(x0, ws[(c0+1)*3+0], fmaf(x1, ws[(c0+1)*3+1], fmaf(x2, ws[(c0+1)*3+2], bs[c0+1]))), 0.f);
            float v2 = fmaxf(fmaf(x0, ws[(c0+2)*3+0], fmaf(x1, ws[(c0+2)*3+1], fmaf(x2, ws[(c0+2)*3+2], bs[c0+2]))), 0.f);
            float v3 = fmaxf(fmaf(x0, ws[(c0+3)*3+0], fmaf(x1, ws[(c0+3)*3+1], fmaf(x2, ws[(c0+3)*3+2], bs[c0+3]))), 0.f);
            out[c0+0] = v0; out[c0+1] = v1; out[c0+2] = v2; out[c0+3] = v3;
            atomicAdd(&msum[c0+0], v0);
            atomicAdd(&msum[c0+1], v1);
            atomicAdd(&msum[c0+2], v2);
            atomicAdd(&msum[c0+3], v3);
        }
    }
    __syncthreads();
    if (t < CH0 && msum[t] != 0.f) atomicAdd(&g_mean0[seq * CH0 + t], msum[t]);
}

// ---------------- 3. cv1 GEMM, tile-stride loop, SE0 MLP in-block, fused SE1 sums ----------------
__global__ void cv1_kernel(const float* __restrict__ cb,
                           const float* __restrict__ s0w1, const float* __restrict__ s0b1,
                           const float* __restrict__ s0w2, const float* __restrict__ s0b2) {
    int seq = blockIdx.y;
    int L = g_len[seq];
    __shared__ __align__(16) float hs[32 * CH0];
    __shared__ __align__(16) float ws[CH0 * CH];
    __shared__ float sred[8 * CH];
    __shared__ float mn0[CH0];
    __shared__ float hid0[4];
    __shared__ float es0[CH0];
    __shared__ float msum1[CH];
    int t = threadIdx.x;
    // SE0 MLP (redundant per block; trivial)
    float inv = 1.f / fmaxf((float)L, 1.f);
    if (t < CH0) mn0[t] = g_mean0[seq * CH0 + t] * inv;
    if (t < CH) msum1[t] = 0.f;
    __syncthreads();
    if (t < 4) {
        float a = s0b1[t];
        for (int k = 0; k < CH0; k++) a = fmaf(mn0[k], s0w1[t * CH0 + k], a);
        hid0[t] = fmaxf(a, 0.f);
    }
    __syncthreads();
    if (t < CH0) {
        float a = s0b2[t];
#pragma unroll
        for (int h = 0; h < 4; h++) a = fmaf(hid0[h], s0w2[t * 4 + h], a);
        es0[t] = sigmoidf_(a);
    }
    __syncthreads();
    for (int idx = t; idx < CH0 * CH; idx += 256)
        ws[idx] = g_cv1T[idx] * es0[idx >> 7];   // fold SE0 gate
    const float* hp = g_h0 + (size_t)seq * SQ * CH0;
    int ty = t >> 5, tx = t & 31;

    for (int j0 = blockIdx.x * 32; j0 < L; j0 += gridDim.x * 32) {
        __syncthreads();   // protect hs/sred reuse across tiles
        for (int idx = t; idx < 32 * CH0; idx += 256) {
            int r = idx >> 6;
            int j = j0 + r;
            hs[idx] = (j < L) ? hp[(size_t)j * CH0 + (idx & 63)] : 0.f;
        }
        __syncthreads();
        float acc[16];
#pragma unroll
        for (int i = 0; i < 16; i++) acc[i] = 0.f;
#pragma unroll 4
        for (int k = 0; k < CH0; k++) {
            float a0 = hs[(ty * 4 + 0) * CH0 + k];
            float a1 = hs[(ty * 4 + 1) * CH0 + k];
            float a2 = hs[(ty * 4 + 2) * CH0 + k];
            float a3 = hs[(ty * 4 + 3) * CH0 + k];
            float4 bv = *(const float4*)&ws[k * CH + tx * 4];
            acc[0]  = fmaf(a0, bv.x, acc[0]);  acc[1]  = fmaf(a0, bv.y, acc[1]);
            acc[2]  = fmaf(a0, bv.z, acc[2]);  acc[3]  = fmaf(a0, bv.w, acc[3]);
            acc[4]  = fmaf(a1, bv.x, acc[4]);  acc[5]  = fmaf(a1, bv.y, acc[5]);
            acc[6]  = fmaf(a1, bv.z, acc[6]);  acc[7]  = fmaf(a1, bv.w, acc[7]);
            acc[8]  = fmaf(a2, bv.x, acc[8]);  acc[9]  = fmaf(a2, bv.y, acc[9]);
            acc[10] = fmaf(a2, bv.z, acc[10]); acc[11] = fmaf(a2, bv.w, acc[11]);
            acc[12] = fmaf(a3, bv.x, acc[12]); acc[13] = fmaf(a3, bv.y, acc[13]);
            acc[14] = fmaf(a3, bv.z, acc[14]); acc[15] = fmaf(a3, bv.w, acc[15]);
        }
        float* out = g_bufA + (size_t)seq * SQ * CH;
        float cs0 = 0.f, cs1 = 0.f, cs2 = 0.f, cs3 = 0.f;
#pragma unroll
        for (int p = 0; p < 4; p++) {
            int j = j0 + ty * 4 + p;
            if (j < L) {
                int c = tx * 4;
                float v0 = fmaxf(acc[p * 4 + 0] + cb[c + 0], 0.f);
                float v1 = fmaxf(acc[p * 4 + 1] + cb[c + 1], 0.f);
                float v2 = fmaxf(acc[p * 4 + 2] + cb[c + 2], 0.f);
                float v3 = fmaxf(acc[p * 4 + 3] + cb[c + 3], 0.f);
                out[(size_t)j * CH + c + 0] = v0;
                out[(size_t)j * CH + c + 1] = v1;
                out[(size_t)j * CH + c + 2] = v2;
                out[(size_t)j * CH + c + 3] = v3;
                cs0 += v0; cs1 += v1; cs2 += v2; cs3 += v3;
            }
        }
        sred[ty * CH + tx * 4 + 0] = cs0;
        sred[ty * CH + tx * 4 + 1] = cs1;
        sred[ty * CH + tx * 4 + 2] = cs2;
        sred[ty * CH + tx * 4 + 3] = cs3;
        __syncthreads();
        if (t < CH) {
            float s = 0.f;
#pragma unroll
            for (int w = 0; w < 8; w++) s += sred[w * CH + t];
            msum1[t] += s;
        }
    }
    __syncthreads();
    if (t < CH && msum1[t] != 0.f) atomicAdd(&g_mean1[seq * CH + t], msum1[t]);
}

// ---------------- 4. residual block, tile-stride loop, cp.async + f32x2 ----------------
__global__ void resblock_kernel(int flip,
                                const float* __restrict__ fw, const float* __restrict__ fb,
                                const float* __restrict__ gw, const float* __restrict__ gb,
                                const float* __restrict__ rb, const float* __restrict__ sb,
                                const float* __restrict__ s1w1, const float* __restrict__ s1b1,
                                const float* __restrict__ s1w2, const float* __restrict__ s1b2,
                                int stack, int skip_init, int applyE, int last) {
    int seq = blockIdx.y;
    int L = g_len[seq];
    const float* hin = flip ? g_bufB : g_bufA;
    float* hout      = flip ? g_bufA : g_bufB;
    const float* rwT = g_rwT + (size_t)stack * CH * CH;
    const float* swT = g_swT + (size_t)stack * CH * CH;

    __shared__ __align__(16) float hs[34 * CH];          // rows j0-1 .. j0+32
    __shared__ __align__(16) float wbuf[2][2][8 * CH];   // [buf][f/g][k2*128+col]
    __shared__ float es[CH];
    __shared__ float mn1[CH];
    __shared__ float hid1[8];

    int t = threadIdx.x;
    int ty = t >> 5, tx = t & 31;
    int ty4 = ty * 4;

    // SE1 gate: compute in-block (redundant; trivial) or identity
    if (applyE) {
        float inv = 1.f / fmaxf((float)L, 1.f);
        if (t < CH) mn1[t] = g_mean1[seq * CH + t] * inv;
        __syncthreads();
        if (t < 8) {
            float a = s1b1[t];
            for (int k = 0; k < CH; k++) a = fmaf(mn1[k], s1w1[t * CH + k], a);
            hid1[t] = fmaxf(a, 0.f);
        }
        __syncthreads();
        if (t < CH) {
            float a = s1b2[t];
#pragma unroll
            for (int h = 0; h < 8; h++) a = fmaf(hid1[h], s1w2[t * 8 + h], a);
            es[t] = sigmoidf_(a);
        }
    } else {
        if (t < CH) es[t] = 1.f;
    }

    const float* hp = hin + (size_t)seq * SQ * CH;
    unsigned wb0 = (unsigned)__cvta_generic_to_shared(&wbuf[0][0][0]);
    float* outr = hout + (size_t)seq * SQ * CH;
    float* outs = g_skip + (size_t)seq * SQ * CH;

    for (int j0 = blockIdx.x * 32; j0 < L; j0 += gridDim.x * 32) {
        __syncthreads();   // es visible (iter 0); protect hs reuse (iter >0)
        {
            const float4* e4 = (const float4*)es;
            float4* hs4 = (float4*)hs;
            for (int idx = t; idx < 34 * 32; idx += 256) {
                int r = idx >> 5;
                int c4 = idx & 31;
                int j = j0 - 1 + r;
                float4 v = make_float4(0.f, 0.f, 0.f, 0.f);
                if (j >= 0 && j < L) {
                    v = ((const float4*)(hp + (size_t)j * CH))[c4];
                    float4 e = e4[c4];
                    v.x *= e.x; v.y *= e.y; v.z *= e.z; v.w *= e.w;
                }
                hs4[idx] = v;
            }
        }

        unsigned long long F0A = 0, F0B = 0, F1A = 0, F1B = 0;
        unsigned long long F2A = 0, F2B = 0, F3A = 0, F3B = 0;
        unsigned long long G0A = 0, G0B = 0, G1A = 0, G1B = 0;
        unsigned long long G2A = 0, G2B = 0, G3A = 0, G3B = 0;

#define STEP(R, AVAL) do {                                                     \
        unsigned long long _ap;                                                \
        PK2(_ap, (AVAL), (AVAL));                                              \
        FMA2(F##R##A, _ap, bfA); FMA2(F##R##B, _ap, bfB);                      \
        FMA2(G##R##A, _ap, bgA); FMA2(G##R##B, _ap, bgB);                      \
    } while (0)

        // ---- phase 1: f/g conv GEMM, K=384 -> 48 chunks of 8 ----
        issue_chunk(wb0, 0, t, fw, gw, 0);
#pragma unroll 1
        for (int c = 0; c < 48; c++) {
            cpwait0();
            __syncthreads();
            if (c < 47) issue_chunk(wb0, (c + 1) & 1, t, fw, gw, c + 1);
            const float* wf = &wbuf[c & 1][0][0];
            const float* wg = &wbuf[c & 1][1][0];
#pragma unroll
            for (int k2 = 0; k2 < 8; k2++) {
                int kk = c * 8 + k2;
                float a0 = hs[(ty4 + 0) * CH + kk];
                float a1 = hs[(ty4 + 1) * CH + kk];
                float a2 = hs[(ty4 + 2) * CH + kk];
                float a3 = hs[(ty4 + 3) * CH + kk];
                ulonglong2 bfp = *(const ulonglong2*)(wf + k2 * CH + tx * 4);
                ulonglong2 bgp = *(const ulonglong2*)(wg + k2 * CH + tx * 4);
                unsigned long long bfA = bfp.x, bfB = bfp.y;
                unsigned long long bgA = bgp.x, bgB = bgp.y;
                STEP(0, a0); STEP(1, a1); STEP(2, a2); STEP(3, a3);
            }
        }
        __syncthreads();   // all hs reads complete

        // ---- gated nonlinearity -> zg tile + prefetch phase-2 chunk 0 ----
        issue_chunk(wb0, 0, t, rwT, swT, 0);
        {
            float4 fbv = ((const float4*)fb)[tx];
            float4 gbv = ((const float4*)gb)[tx];
#define GATE(R, ROW) do {                                                      \
            float fx, fy, fz, fw_, gx, gy, gz, gw_;                            \
            UPK2(fx, fy, F##R##A); UPK2(fz, fw_, F##R##B);                     \
            UPK2(gx, gy, G##R##A); UPK2(gz, gw_, G##R##B);                     \
            float4 z;                                                          \
            z.x = tanhf(fx + fbv.x) * sigmoidf_(gx + gbv.x);                   \
            z.y = tanhf(fy + fbv.y) * sigmoidf_(gy + gbv.y);                   \
            z.z = tanhf(fz + fbv.z) * sigmoidf_(gz + gbv.z);                   \
            z.w = tanhf(fw_ + fbv.w) * sigmoidf_(gw_ + gbv.w);                 \
            ((float4*)&hs[(ty4 + (ROW)) * CH])[tx] = z;                        \
        } while (0)
            GATE(0, 0); GATE(1, 1); GATE(2, 2); GATE(3, 3);
#undef GATE
        }
        F0A = F0B = F1A = F1B = F2A = F2B = F3A = F3B = 0ull;
        G0A = G0B = G1A = G1B = G2A = G2B = G3A = G3B = 0ull;

        // ---- phase 2: res/skip GEMM, K=128 -> 16 chunks of 8 ----
#pragma unroll 1
        for (int c = 0; c < 16; c++) {
            cpwait0();
            __syncthreads();   // (c==0: also orders zg writes before reads)
            if (c < 15) issue_chunk(wb0, (c + 1) & 1, t, rwT, swT, c + 1);
            const float* wf = &wbuf[c & 1][0][0];
            const float* wg = &wbuf[c & 1][1][0];
#pragma unroll
            for (int k2 = 0; k2 < 8; k2++) {
                int kk = c * 8 + k2;
                float a0 = hs[(ty4 + 0) * CH + kk];
                float a1 = hs[(ty4 + 1) * CH + kk];
                float a2 = hs[(ty4 + 2) * CH + kk];
                float a3 = hs[(ty4 + 3) * CH + kk];
                ulonglong2 bfp = *(const ulonglong2*)(wf + k2 * CH + tx * 4);
                ulonglong2 bgp = *(const ulonglong2*)(wg + k2 * CH + tx * 4);
                unsigned long long bfA = bfp.x, bfB = bfp.y;
                unsigned long long bgA = bgp.x, bgB = bgp.y;
                STEP(0, a0); STEP(1, a1); STEP(2, a2); STEP(3, a3);
            }
        }
#undef STEP

        // ---- epilogue ----
        float4 rbv = ((const float4*)rb)[tx];
        float4 sbv = ((const float4*)sb)[tx];
        float4 ev  = ((const float4*)es)[tx];

#define EPILOG(ROW, FA_, FB_, GA_, GB_)                                          \
    do {                                                                         \
        int j = j0 + ty4 + (ROW);                                                \
        if (j < L) {                                                             \
            float fx, fy, fz, fw_, gx, gy, gz, gw_;                              \
            UPK2(fx, fy, FA_); UPK2(fz, fw_, FB_);                               \
            UPK2(gx, gy, GA_); UPK2(gz, gw_, GB_);                               \
            float4 hv = ((const float4*)(hp + (size_t)j * CH))[tx];              \
            float4 o;                                                            \
            o.x = fx + rbv.x + hv.x * ev.x;                                      \
            o.y = fy + rbv.y + hv.y * ev.y;                                      \
            o.z = fz + rbv.z + hv.z * ev.z;                                      \
            o.w = fw_ + rbv.w + hv.w * ev.w;                                     \
            float4 s;                                                            \
            s.x = gx + sbv.x; s.y = gy + sbv.y;                                  \
            s.z = gz + sbv.z; s.w = gw_ + sbv.w;                                 \
            if (!skip_init) {                                                    \
                float4 old = ((const float4*)(outs + (size_t)j * CH))[tx];       \
                s.x += old.x; s.y += old.y; s.z += old.z; s.w += old.w;          \
            }                                                                    \
            if (last) {                                                          \
                s.x += o.x; s.y += o.y; s.z += o.z; s.w += o.w;                  \
                ((float4*)(outs + (size_t)j * CH))[tx] = s;                      \
            } else {                                                             \
                ((float4*)(outr + (size_t)j * CH))[tx] = o;                      \
                ((float4*)(outs + (size_t)j * CH))[tx] = s;                      \
            }                                                                    \
        }                                                                        \
    } while (0)

        EPILOG(0, F0A, F0B, G0A, G0B);
        EPILOG(1, F1A, F1B, G1A, G1B);
        EPILOG(2, F2A, F2B, G2A, G2B);
        EPILOG(3, F3A, F3B, G3A, G3B);
#undef EPILOG
    }
}

// ---------------- 5. fused masked avg/max pool + head MLP ----------------
__global__ void finalhead_kernel(const float* __restrict__ l1w, const float* __restrict__ l1b,
                                 const float* __restrict__ l2w, const float* __restrict__ l2b,
                                 float* __restrict__ out) {
    int seq = blockIdx.x;
    int L = g_len[seq];
    int t = threadIdx.x;
    __shared__ float ssum[256], smx[256];
    __shared__ float fs[256];
    __shared__ float r0[256], r1[256];
    {
        int c = t & 127, half = t >> 7;
        const float* s = g_skip + (size_t)seq * SQ * CH + c;
        float sum = 0.f, mx = -INFINITY;
        for (int j = half; j < L; j += 2) {
            float v = s[(size_t)j * CH];
            sum += v;
            mx = fmaxf(mx, v);
        }
        ssum[t] = sum; smx[t] = mx;
    }
    __syncthreads();
    if (t < 128) {
        float su = ssum[t] + ssum[t + 128];
        float m = fmaxf(smx[t], smx[t + 128]);
        if (L == 0) m = 0.f;
        float cnt = fmaxf((float)L, 1.f);
        fs[2 * t]     = su / cnt;
        fs[2 * t + 1] = m;
    }
    __syncthreads();
    float o0 = 0.f, o1 = 0.f;
    for (int u = t; u < 1024; u += 256) {
        const float* w = l1w + (size_t)u * 256;
        float a = l1b[u];
#pragma unroll 8
        for (int v = 0; v < 256; v++) a = fmaf(fs[v], w[v], a);
        float hv = fmaxf(a, 0.f);
        o0 = fmaf(hv, l2w[u], o0);
        o1 = fmaf(hv, l2w[1024 + u], o1);
    }
    r0[t] = o0; r1[t] = o1;
    __syncthreads();
    for (int st = 128; st > 0; st >>= 1) {
        if (t < st) { r0[t] += r0[t + st]; r1[t] += r1[t + st]; }
        __syncthreads();
    }
    if (t == 0) {
        out[seq * 2 + 0] = r0[0] + l2b[0];
        out[seq * 2 + 1] = r1[0] + l2b[1];
    }
}

// ---------------- launch ----------------
extern "C" void kernel_launch(void* const* d_in, const int* in_sizes, int n_in,
                              void* d_out, int out_size) {
    const float* raw    = (const float*)d_in[0];
    const int*   labels = (const int*)  d_in[1];
    const float* cv0_w  = (const float*)d_in[2];
    const float* cv0_b  = (const float*)d_in[3];
    const float* se0_w1 = (const float*)d_in[4];
    const float* se0_b1 = (const float*)d_in[5];
    const float* se0_w2 = (const float*)d_in[6];
    const float* se0_b2 = (const float*)d_in[7];
    const float* cv1_w  = (const float*)d_in[8];
    const float* cv1_b  = (const float*)d_in[9];
    const float* se1_w1 = (const float*)d_in[10];
    const float* se1_b1 = (const float*)d_in[11];
    const float* se1_w2 = (const float*)d_in[12];
    const float* se1_b2 = (const float*)d_in[13];
    const float* rs_fw  = (const float*)d_in[14];
    const float* rs_fb  = (const float*)d_in[15];
    const float* rs_gw  = (const float*)d_in[16];
    const float* rs_gb  = (const float*)d_in[17];
    const float* rs_rw  = (const float*)d_in[18];
    const float* rs_rb  = (const float*)d_in[19];
    const float* rs_sw  = (const float*)d_in[20];
    const float* rs_sb  = (const float*)d_in[21];
    const float* l1_w   = (const float*)d_in[22];
    const float* l1_b   = (const float*)d_in[23];
    const float* l2_w   = (const float*)d_in[24];
    const float* l2_b   = (const float*)d_in[25];
    float* out = (float*)d_out;

    gather_kernel<<<NSEQ, 256>>>(raw, labels);
    prep_kernel<<<192, 256>>>(cv1_w, rs_rw, rs_sw);
    cv0_kernel<<<dim3(32, NSEQ), 256>>>(cv0_w, cv0_b);
    cv1_kernel<<<dim3(16, NSEQ), 256>>>(cv1_b, se0_w1, se0_b1, se0_w2, se0_b2);

    for (int st = 0; st < 3; st++) {
        int flip = st & 1;  // 0: A->B, 1: B->A, 2: A->(fused into g_skip)
        resblock_kernel<<<dim3(16, NSEQ), 256>>>(
            flip,
            rs_fw + (size_t)st * 3 * CH * CH, rs_fb + st * CH,
            rs_gw + (size_t)st * 3 * CH * CH, rs_gb + st * CH,
            rs_rb + st * CH, rs_sb + st * CH,
            se1_w1, se1_b1, se1_w2, se1_b2,
            st, st == 0, st == 0, st == 2);
    }
    finalhead_kernel<<<NSEQ, 256>>>(l1_w, l1_b, l2_w, l2_b, out);
}

// round 14
// speedup vs baseline: 1.0558x; 1.0558x over previous
#include <cuda_runtime.h>
#include <cstdint>
#include <math.h>

#define SQ   4096
#define NSEQ 80
#define CH   128
#define CH0  64

// ---------------- device scratch ----------------
__device__ int   g_len[NSEQ];
__device__ float g_x[NSEQ * SQ * 3];
__device__ float g_h0[(size_t)NSEQ * SQ * CH0];
__device__ float g_bufA[(size_t)NSEQ * SQ * CH];
__device__ float g_bufB[(size_t)NSEQ * SQ * CH];
__device__ float g_skip[(size_t)NSEQ * SQ * CH];
__device__ float g_mean0[NSEQ * CH0];
__device__ float g_mean1[NSEQ * CH];
__device__ float g_cv1T[CH0 * CH];       // cv1_w transposed [k][o]
__device__ float g_rwT[3 * CH * CH];     // rs_rw transposed per stack [k][o]
__device__ float g_swT[3 * CH * CH];

__device__ __forceinline__ float sigmoidf_(float x) { return 1.f / (1.f + expf(-x)); }

__device__ __forceinline__ void cpasync16(unsigned saddr, const void* gptr) {
    asm volatile("cp.async.cg.shared.global [%0], [%1], 16;" :: "r"(saddr), "l"(gptr));
}
__device__ __forceinline__ void cpcommit() { asm volatile("cp.async.commit_group;"); }
__device__ __forceinline__ void cpwait0()  { asm volatile("cp.async.wait_group 0;" ::: "memory"); }

// stage chunk c (8 k-rows = 256 float4 per matrix) of two weight matrices into wbuf[buf]
__device__ __forceinline__ void issue_chunk(unsigned wb0, int buf, int t,
                                            const float* fsrc, const float* gsrc, int c) {
    unsigned d = wb0 + (unsigned)buf * 8192u + (unsigned)t * 16u;
    cpasync16(d,         (const float4*)fsrc + c * 256 + t);
    cpasync16(d + 4096u, (const float4*)gsrc + c * 256 + t);
    cpcommit();
}

// ---- packed f32x2 helpers ----
#define PK2(D, LO, HI) \
    asm("mov.b64 %0, {%1, %2};" : "=l"(D) : "f"(LO), "f"(HI))
#define UPK2(LO, HI, S) \
    asm("mov.b64 {%0, %1}, %2;" : "=f"(LO), "=f"(HI) : "l"(S))
#define FMA2(ACC, A, W) \
    asm("fma.rn.f32x2 %0, %1, %2, %0;" : "+l"(ACC) : "l"(A), "l"(W))

// ---------------- 1. stable gather per (batch, class) + zero mean buffers ----------------
__global__ void gather_kernel(const float* __restrict__ raw, const int* __restrict__ labels) {
    int seq = blockIdx.x;
    int b = seq / 10, cls = seq % 10 + 1;
    const int* lab = labels + b * SQ;
    __shared__ int cnt[256];
    __shared__ int scan[257];
    int t = threadIdx.x;
    if (t < CH0) g_mean0[seq * CH0 + t] = 0.f;
    if (t < CH)  g_mean1[seq * CH + t]  = 0.f;
    int base = t * 16;
    int c = 0;
#pragma unroll
    for (int u = 0; u < 16; u++) c += (lab[base + u] == cls);
    cnt[t] = c;
    __syncthreads();
    if (t == 0) {
        int acc = 0;
        for (int i = 0; i < 256; i++) { scan[i] = acc; acc += cnt[i]; }
        scan[256] = acc;
        g_len[seq] = acc;
    }
    __syncthreads();
    int w = scan[t];
    const float* xb = raw + (size_t)b * SQ * 3;
    float* dst = g_x + (size_t)seq * SQ * 3;
    for (int u = 0; u < 16; u++) {
        int s = base + u;
        if (lab[s] == cls) {
            dst[w * 3 + 0] = xb[s * 3 + 0];
            dst[w * 3 + 1] = xb[s * 3 + 1];
            dst[w * 3 + 2] = xb[s * 3 + 2];
            w++;
        }
    }
}

// ---------------- prep: transpose small weight matrices ----------------
__global__ void prep_kernel(const float* __restrict__ cv1_w,
                            const float* __restrict__ rw, const float* __restrict__ sw) {
    int idx = blockIdx.x * 256 + threadIdx.x;
    if (idx < CH0 * CH) {
        int k = idx / CH, o = idx % CH;
        g_cv1T[idx] = cv1_w[o * CH0 + k];
    }
    if (idx < 3 * CH * CH) {
        int st = idx / (CH * CH);
        int r = idx % (CH * CH);
        int k = r / CH, o = r % CH;
        g_rwT[idx] = rw[(size_t)st * CH * CH + o * CH + k];
        g_swT[idx] = sw[(size_t)st * CH * CH + o * CH + k];
    }
}

// ---------------- 2. cv0 (K=3), tile-stride loop, fused SE0 mean partial-sums ----------------
__global__ void cv0_kernel(const float* __restrict__ w, const float* __restrict__ b) {
    int seq = blockIdx.y;
    int L = g_len[seq];
    __shared__ float ws[CH0 * 3];
    __shared__ float bs[CH0];
    __shared__ float msum[CH0];
    int t = threadIdx.x;
    if (t < CH0 * 3) ws[t] = w[t];
    if (t < CH0) { bs[t] = b[t]; msum[t] = 0.f; }
    __syncthreads();
    int c0 = (t & 15) * 4;
    for (int j0 = blockIdx.x * 16; j0 < L; j0 += gridDim.x * 16) {
        int j = j0 + (t >> 4);
        if (j < L) {
            const float* xp = g_x + ((size_t)seq * SQ + j) * 3;
            float x0 = xp[0], x1 = xp[1], x2 = xp[2];
            float* out = g_h0 + ((size_t)seq * SQ + j) * CH0;
            float v0 = fmaxf(fmaf(x0, ws[(c0+0)*3+0], fmaf(x1, ws[(c0+0)*3+1], fmaf(x2, ws[(c0+0)*3+2], bs[c0+0]))), 0.f);
            float v1 = fmaxf(fmaf(x0, ws[(c0+1)*3+0], fmaf(x1, ws[(c0+1)*3+1], fmaf(x2, ws[(c0+1)*3+2], bs[c0+1]))), 0.f);
            float v2 = fmaxf(fmaf(x0, ws[(c0+2)*3+0], fmaf(x1, ws[(c0+2)*3+1], fmaf(x2, ws[(c0+2)*3+2], bs[c0+2]))), 0.f);
            float v3 = fmaxf(fmaf(x0, ws[(c0+3)*3+0], fmaf(x1, ws[(c0+3)*3+1], fmaf(x2, ws[(c0+3)*3+2], bs[c0+3]))), 0.f);
            out[c0+0] = v0; out[c0+1] = v1; out[c0+2] = v2; out[c0+3] = v3;
            atomicAdd(&msum[c0+0], v0);
            atomicAdd(&msum[c0+1], v1);
            atomicAdd(&msum[c0+2], v2);
            atomicAdd(&msum[c0+3], v3);
        }
    }
    __syncthreads();
    if (t < CH0 && msum[t] != 0.f) atomicAdd(&g_mean0[seq * CH0 + t], msum[t]);
}

// ---------------- 3. cv1 GEMM, tile-stride loop, SE0 MLP in-block, fused SE1 sums ----------------
__global__ void cv1_kernel(const float* __restrict__ cb,
                           const float* __restrict__ s0w1, const float* __restrict__ s0b1,
                           const float* __restrict__ s0w2, const float* __restrict__ s0b2) {
    int seq = blockIdx.y;
    int L = g_len[seq];
    __shared__ __align__(16) float hs[32 * CH0];
    __shared__ __align__(16) float ws[CH0 * CH];
    __shared__ float sred[8 * CH];
    __shared__ float mn0[CH0];
    __shared__ float hid0[4];
    __shared__ float es0[CH0];
    __shared__ float msum1[CH];
    int t = threadIdx.x;
    float inv = 1.f / fmaxf((float)L, 1.f);
    if (t < CH0) mn0[t] = g_mean0[seq * CH0 + t] * inv;
    if (t < CH) msum1[t] = 0.f;
    __syncthreads();
    if (t < 4) {
        float a = s0b1[t];
        for (int k = 0; k < CH0; k++) a = fmaf(mn0[k], s0w1[t * CH0 + k], a);
        hid0[t] = fmaxf(a, 0.f);
    }
    __syncthreads();
    if (t < CH0) {
        float a = s0b2[t];
#pragma unroll
        for (int h = 0; h < 4; h++) a = fmaf(hid0[h], s0w2[t * 4 + h], a);
        es0[t] = sigmoidf_(a);
    }
    __syncthreads();
    for (int idx = t; idx < CH0 * CH; idx += 256)
        ws[idx] = g_cv1T[idx] * es0[idx >> 7];   // fold SE0 gate
    const float* hp = g_h0 + (size_t)seq * SQ * CH0;
    int ty = t >> 5, tx = t & 31;

    for (int j0 = blockIdx.x * 32; j0 < L; j0 += gridDim.x * 32) {
        __syncthreads();
        for (int idx = t; idx < 32 * CH0; idx += 256) {
            int r = idx >> 6;
            int j = j0 + r;
            hs[idx] = (j < L) ? hp[(size_t)j * CH0 + (idx & 63)] : 0.f;
        }
        __syncthreads();
        float acc[16];
#pragma unroll
        for (int i = 0; i < 16; i++) acc[i] = 0.f;
#pragma unroll 4
        for (int k = 0; k < CH0; k++) {
            float a0 = hs[(ty * 4 + 0) * CH0 + k];
            float a1 = hs[(ty * 4 + 1) * CH0 + k];
            float a2 = hs[(ty * 4 + 2) * CH0 + k];
            float a3 = hs[(ty * 4 + 3) * CH0 + k];
            float4 bv = *(const float4*)&ws[k * CH + tx * 4];
            acc[0]  = fmaf(a0, bv.x, acc[0]);  acc[1]  = fmaf(a0, bv.y, acc[1]);
            acc[2]  = fmaf(a0, bv.z, acc[2]);  acc[3]  = fmaf(a0, bv.w, acc[3]);
            acc[4]  = fmaf(a1, bv.x, acc[4]);  acc[5]  = fmaf(a1, bv.y, acc[5]);
            acc[6]  = fmaf(a1, bv.z, acc[6]);  acc[7]  = fmaf(a1, bv.w, acc[7]);
            acc[8]  = fmaf(a2, bv.x, acc[8]);  acc[9]  = fmaf(a2, bv.y, acc[9]);
            acc[10] = fmaf(a2, bv.z, acc[10]); acc[11] = fmaf(a2, bv.w, acc[11]);
            acc[12] = fmaf(a3, bv.x, acc[12]); acc[13] = fmaf(a3, bv.y, acc[13]);
            acc[14] = fmaf(a3, bv.z, acc[14]); acc[15] = fmaf(a3, bv.w, acc[15]);
        }
        float* out = g_bufA + (size_t)seq * SQ * CH;
        float cs0 = 0.f, cs1 = 0.f, cs2 = 0.f, cs3 = 0.f;
#pragma unroll
        for (int p = 0; p < 4; p++) {
            int j = j0 + ty * 4 + p;
            if (j < L) {
                int c = tx * 4;
                float v0 = fmaxf(acc[p * 4 + 0] + cb[c + 0], 0.f);
                float v1 = fmaxf(acc[p * 4 + 1] + cb[c + 1], 0.f);
                float v2 = fmaxf(acc[p * 4 + 2] + cb[c + 2], 0.f);
                float v3 = fmaxf(acc[p * 4 + 3] + cb[c + 3], 0.f);
                out[(size_t)j * CH + c + 0] = v0;
                out[(size_t)j * CH + c + 1] = v1;
                out[(size_t)j * CH + c + 2] = v2;
                out[(size_t)j * CH + c + 3] = v3;
                cs0 += v0; cs1 += v1; cs2 += v2; cs3 += v3;
            }
        }
        sred[ty * CH + tx * 4 + 0] = cs0;
        sred[ty * CH + tx * 4 + 1] = cs1;
        sred[ty * CH + tx * 4 + 2] = cs2;
        sred[ty * CH + tx * 4 + 3] = cs3;
        __syncthreads();
        if (t < CH) {
            float s = 0.f;
#pragma unroll
            for (int w = 0; w < 8; w++) s += sred[w * CH + t];
            msum1[t] += s;
        }
    }
    __syncthreads();
    if (t < CH && msum1[t] != 0.f) atomicAdd(&g_mean1[seq * CH + t], msum1[t]);
}

// ---------------- 4. residual block: one tile/block (R12), vectorized a-loads ----------------
__global__ void resblock_kernel(int flip,
                                const float* __restrict__ fw, const float* __restrict__ fb,
                                const float* __restrict__ gw, const float* __restrict__ gb,
                                const float* __restrict__ rb, const float* __restrict__ sb,
                                const float* __restrict__ s1w1, const float* __restrict__ s1b1,
                                const float* __restrict__ s1w2, const float* __restrict__ s1b2,
                                int stack, int skip_init, int applyE, int last) {
    int seq = blockIdx.y;
    int L = g_len[seq];
    int j0 = blockIdx.x * 32;
    if (j0 >= L) return;
    const float* hin = flip ? g_bufB : g_bufA;
    float* hout      = flip ? g_bufA : g_bufB;
    const float* rwT = g_rwT + (size_t)stack * CH * CH;
    const float* swT = g_swT + (size_t)stack * CH * CH;

    __shared__ __align__(16) float hs[34 * CH];
    __shared__ __align__(16) float wbuf[2][2][8 * CH];
    __shared__ float es[CH];
    __shared__ float mn1[CH];
    __shared__ float hid1[8];

    int t = threadIdx.x;
    int ty = t >> 5, tx = t & 31;
    int ty4 = ty * 4;

    if (applyE) {
        float inv = 1.f / fmaxf((float)L, 1.f);
        if (t < CH) mn1[t] = g_mean1[seq * CH + t] * inv;
        __syncthreads();
        if (t < 8) {
            float a = s1b1[t];
            for (int k = 0; k < CH; k++) a = fmaf(mn1[k], s1w1[t * CH + k], a);
            hid1[t] = fmaxf(a, 0.f);
        }
        __syncthreads();
        if (t < CH) {
            float a = s1b2[t];
#pragma unroll
            for (int h = 0; h < 8; h++) a = fmaf(hid1[h], s1w2[t * 8 + h], a);
            es[t] = sigmoidf_(a);
        }
    } else {
        if (t < CH) es[t] = 1.f;
    }
    __syncthreads();

    const float* hp = hin + (size_t)seq * SQ * CH;
    {
        const float4* e4 = (const float4*)es;
        float4* hs4 = (float4*)hs;
        for (int idx = t; idx < 34 * 32; idx += 256) {
            int r = idx >> 5;
            int c4 = idx & 31;
            int j = j0 - 1 + r;
            float4 v = make_float4(0.f, 0.f, 0.f, 0.f);
            if (j >= 0 && j < L) {
                v = ((const float4*)(hp + (size_t)j * CH))[c4];
                float4 e = e4[c4];
                v.x *= e.x; v.y *= e.y; v.z *= e.z; v.w *= e.w;
            }
            hs4[idx] = v;
        }
    }

    unsigned wb0 = (unsigned)__cvta_generic_to_shared(&wbuf[0][0][0]);

    unsigned long long F0A = 0, F0B = 0, F1A = 0, F1B = 0;
    unsigned long long F2A = 0, F2B = 0, F3A = 0, F3B = 0;
    unsigned long long G0A = 0, G0B = 0, G1A = 0, G1B = 0;
    unsigned long long G2A = 0, G2B = 0, G3A = 0, G3B = 0;

#define STEP(R, AVAL) do {                                                     \
        unsigned long long _ap;                                                \
        PK2(_ap, (AVAL), (AVAL));                                              \
        FMA2(F##R##A, _ap, bfA); FMA2(F##R##B, _ap, bfB);                      \
        FMA2(G##R##A, _ap, bgA); FMA2(G##R##B, _ap, bgB);                      \
    } while (0)
#define SEL(V, KQ) ((KQ) == 0 ? (V).x : (KQ) == 1 ? (V).y : (KQ) == 2 ? (V).z : (V).w)

    // ---- phase 1: f/g conv GEMM, K=384 -> 48 chunks of 8 ----
    issue_chunk(wb0, 0, t, fw, gw, 0);
#pragma unroll 1
    for (int c = 0; c < 48; c++) {
        cpwait0();
        __syncthreads();
        if (c < 47) issue_chunk(wb0, (c + 1) & 1, t, fw, gw, c + 1);
        const float* wf = &wbuf[c & 1][0][0];
        const float* wg = &wbuf[c & 1][1][0];
#pragma unroll
        for (int k4 = 0; k4 < 2; k4++) {
            int kb = c * 8 + k4 * 4;
            float4 a0v = *(const float4*)&hs[(ty4 + 0) * CH + kb];
            float4 a1v = *(const float4*)&hs[(ty4 + 1) * CH + kb];
            float4 a2v = *(const float4*)&hs[(ty4 + 2) * CH + kb];
            float4 a3v = *(const float4*)&hs[(ty4 + 3) * CH + kb];
#pragma unroll
            for (int kq = 0; kq < 4; kq++) {
                int k2 = k4 * 4 + kq;
                ulonglong2 bfp = *(const ulonglong2*)(wf + k2 * CH + tx * 4);
                ulonglong2 bgp = *(const ulonglong2*)(wg + k2 * CH + tx * 4);
                unsigned long long bfA = bfp.x, bfB = bfp.y;
                unsigned long long bgA = bgp.x, bgB = bgp.y;
                STEP(0, SEL(a0v, kq)); STEP(1, SEL(a1v, kq));
                STEP(2, SEL(a2v, kq)); STEP(3, SEL(a3v, kq));
            }
        }
    }
    __syncthreads();

    // ---- gated nonlinearity -> zg tile + prefetch phase-2 chunk 0 ----
    issue_chunk(wb0, 0, t, rwT, swT, 0);
    {
        float4 fbv = ((const float4*)fb)[tx];
        float4 gbv = ((const float4*)gb)[tx];
#define GATE(R, ROW) do {                                                      \
            float fx, fy, fz, fw_, gx, gy, gz, gw_;                            \
            UPK2(fx, fy, F##R##A); UPK2(fz, fw_, F##R##B);                     \
            UPK2(gx, gy, G##R##A); UPK2(gz, gw_, G##R##B);                     \
            float4 z;                                                          \
            z.x = tanhf(fx + fbv.x) * sigmoidf_(gx + gbv.x);                   \
            z.y = tanhf(fy + fbv.y) * sigmoidf_(gy + gbv.y);                   \
            z.z = tanhf(fz + fbv.z) * sigmoidf_(gz + gbv.z);                   \
            z.w = tanhf(fw_ + fbv.w) * sigmoidf_(gw_ + gbv.w);                 \
            ((float4*)&hs[(ty4 + (ROW)) * CH])[tx] = z;                        \
        } while (0)
        GATE(0, 0); GATE(1, 1); GATE(2, 2); GATE(3, 3);
#undef GATE
    }
    F0A = F0B = F1A = F1B = F2A = F2B = F3A = F3B = 0ull;
    G0A = G0B = G1A = G1B = G2A = G2B = G3A = G3B = 0ull;

    // ---- phase 2: res/skip GEMM, K=128 -> 16 chunks of 8 ----
#pragma unroll 1
    for (int c = 0; c < 16; c++) {
        cpwait0();
        __syncthreads();
        if (c < 15) issue_chunk(wb0, (c + 1) & 1, t, rwT, swT, c + 1);
        const float* wf = &wbuf[c & 1][0][0];
        const float* wg = &wbuf[c & 1][1][0];
#pragma unroll
        for (int k4 = 0; k4 < 2; k4++) {
            int kb = c * 8 + k4 * 4;
            float4 a0v = *(const float4*)&hs[(ty4 + 0) * CH + kb];
            float4 a1v = *(const float4*)&hs[(ty4 + 1) * CH + kb];
            float4 a2v = *(const float4*)&hs[(ty4 + 2) * CH + kb];
            float4 a3v = *(const float4*)&hs[(ty4 + 3) * CH + kb];
#pragma unroll
            for (int kq = 0; kq < 4; kq++) {
                int k2 = k4 * 4 + kq;
                ulonglong2 bfp = *(const ulonglong2*)(wf + k2 * CH + tx * 4);
                ulonglong2 bgp = *(const ulonglong2*)(wg + k2 * CH + tx * 4);
                unsigned long long bfA = bfp.x, bfB = bfp.y;
                unsigned long long bgA = bgp.x, bgB = bgp.y;
                STEP(0, SEL(a0v, kq)); STEP(1, SEL(a1v, kq));
                STEP(2, SEL(a2v, kq)); STEP(3, SEL(a3v, kq));
            }
        }
    }
#undef STEP
#undef SEL

    // ---- epilogue ----
    float* outr = hout + (size_t)seq * SQ * CH;
    float* outs = g_skip + (size_t)seq * SQ * CH;
    float4 rbv = ((const float4*)rb)[tx];
    float4 sbv = ((const float4*)sb)[tx];
    float4 ev  = ((const float4*)es)[tx];

#define EPILOG(ROW, FA_, FB_, GA_, GB_)                                          \
    do {                                                                         \
        int j = j0 + ty4 + (ROW);                                                \
        if (j < L) {                                                             \
            float fx, fy, fz, fw_, gx, gy, gz, gw_;                              \
            UPK2(fx, fy, FA_); UPK2(fz, fw_, FB_);                               \
            UPK2(gx, gy, GA_); UPK2(gz, gw_, GB_);                               \
            float4 hv = ((const float4*)(hp + (size_t)j * CH))[tx];              \
            float4 o;                                                            \
            o.x = fx + rbv.x + hv.x * ev.x;                                      \
            o.y = fy + rbv.y + hv.y * ev.y;                                      \
            o.z = fz + rbv.z + hv.z * ev.z;                                      \
            o.w = fw_ + rbv.w + hv.w * ev.w;                                     \
            float4 s;                                                            \
            s.x = gx + sbv.x; s.y = gy + sbv.y;                                  \
            s.z = gz + sbv.z; s.w = gw_ + sbv.w;                                 \
            if (!skip_init) {                                                    \
                float4 old = ((const float4*)(outs + (size_t)j * CH))[tx];       \
                s.x += old.x; s.y += old.y; s.z += old.z; s.w += old.w;          \
            }                                                                    \
            if (last) {                                                          \
                s.x += o.x; s.y += o.y; s.z += o.z; s.w += o.w;                  \
                ((float4*)(outs + (size_t)j * CH))[tx] = s;                      \
            } else {                                                             \
                ((float4*)(outr + (size_t)j * CH))[tx] = o;                      \
                ((float4*)(outs + (size_t)j * CH))[tx] = s;                      \
            }                                                                    \
        }                                                                        \
    } while (0)

    EPILOG(0, F0A, F0B, G0A, G0B);
    EPILOG(1, F1A, F1B, G1A, G1B);
    EPILOG(2, F2A, F2B, G2A, G2B);
    EPILOG(3, F3A, F3B, G3A, G3B);
#undef EPILOG
}

// ---------------- 5. fused masked avg/max pool + head MLP ----------------
__global__ void finalhead_kernel(const float* __restrict__ l1w, const float* __restrict__ l1b,
                                 const float* __restrict__ l2w, const float* __restrict__ l2b,
                                 float* __restrict__ out) {
    int seq = blockIdx.x;
    int L = g_len[seq];
    int t = threadIdx.x;
    __shared__ float ssum[256], smx[256];
    __shared__ float fs[256];
    __shared__ float r0[256], r1[256];
    {
        int c = t & 127, half = t >> 7;
        const float* s = g_skip + (size_t)seq * SQ * CH + c;
        float sum = 0.f, mx = -INFINITY;
        for (int j = half; j < L; j += 2) {
            float v = s[(size_t)j * CH];
            sum += v;
            mx = fmaxf(mx, v);
        }
        ssum[t] = sum; smx[t] = mx;
    }
    __syncthreads();
    if (t < 128) {
        float su = ssum[t] + ssum[t + 128];
        float m = fmaxf(smx[t], smx[t + 128]);
        if (L == 0) m = 0.f;
        float cnt = fmaxf((float)L, 1.f);
        fs[2 * t]     = su / cnt;
        fs[2 * t + 1] = m;
    }
    __syncthreads();
    float o0 = 0.f, o1 = 0.f;
    for (int u = t; u < 1024; u += 256) {
        const float* w = l1w + (size_t)u * 256;
        float a = l1b[u];
#pragma unroll 8
        for (int v = 0; v < 256; v++) a = fmaf(fs[v], w[v], a);
        float hv = fmaxf(a, 0.f);
        o0 = fmaf(hv, l2w[u], o0);
        o1 = fmaf(hv, l2w[1024 + u], o1);
    }
    r0[t] = o0; r1[t] = o1;
    __syncthreads();
    for (int st = 128; st > 0; st >>= 1) {
        if (t < st) { r0[t] += r0[t + st]; r1[t] += r1[t + st]; }
        __syncthreads();
    }
    if (t == 0) {
        out[seq * 2 + 0] = r0[0] + l2b[0];
        out[seq * 2 + 1] = r1[0] + l2b[1];
    }
}

// ---------------- launch ----------------
extern "C" void kernel_launch(void* const* d_in, const int* in_sizes, int n_in,
                              void* d_out, int out_size) {
    const float* raw    = (const float*)d_in[0];
    const int*   labels = (const int*)  d_in[1];
    const float* cv0_w  = (const float*)d_in[2];
    const float* cv0_b  = (const float*)d_in[3];
    const float* se0_w1 = (const float*)d_in[4];
    const float* se0_b1 = (const float*)d_in[5];
    const float* se0_w2 = (const float*)d_in[6];
    const float* se0_b2 = (const float*)d_in[7];
    const float* cv1_w  = (const float*)d_in[8];
    const float* cv1_b  = (const float*)d_in[9];
    const float* se1_w1 = (const float*)d_in[10];
    const float* se1_b1 = (const float*)d_in[11];
    const float* se1_w2 = (const float*)d_in[12];
    const float* se1_b2 = (const float*)d_in[13];
    const float* rs_fw  = (const float*)d_in[14];
    const float* rs_fb  = (const float*)d_in[15];
    const float* rs_gw  = (const float*)d_in[16];
    const float* rs_gb  = (const float*)d_in[17];
    const float* rs_rw  = (const float*)d_in[18];
    const float* rs_rb  = (const float*)d_in[19];
    const float* rs_sw  = (const float*)d_in[20];
    const float* rs_sb  = (const float*)d_in[21];
    const float* l1_w   = (const float*)d_in[22];
    const float* l1_b   = (const float*)d_in[23];
    const float* l2_w   = (const float*)d_in[24];
    const float* l2_b   = (const float*)d_in[25];
    float* out = (float*)d_out;

    gather_kernel<<<NSEQ, 256>>>(raw, labels);
    prep_kernel<<<192, 256>>>(cv1_w, rs_rw, rs_sw);
    cv0_kernel<<<dim3(32, NSEQ), 256>>>(cv0_w, cv0_b);
    cv1_kernel<<<dim3(16, NSEQ), 256>>>(cv1_b, se0_w1, se0_b1, se0_w2, se0_b2);

    for (int st = 0; st < 3; st++) {
        int flip = st & 1;  // 0: A->B, 1: B->A, 2: A->(fused into g_skip)
        resblock_kernel<<<dim3(128, NSEQ), 256>>>(
            flip,
            rs_fw + (size_t)st * 3 * CH * CH, rs_fb + st * CH,
            rs_gw + (size_t)st * 3 * CH * CH, rs_gb + st * CH,
            rs_rb + st * CH, rs_sb + st * CH,
            se1_w1, se1_b1, se1_w2, se1_b2,
            st, st == 0, st == 0, st == 2);
    }
    finalhead_kernel<<<NSEQ, 256>>>(l1_w, l1_b, l2_w, l2_b, out);
}

// round 15
// speedup vs baseline: 1.7178x; 1.6270x over previous
#include <cuda_runtime.h>
#include <cstdint>
#include <math.h>

#define SQ   4096
#define NSEQ 80
#define CH   128
#define CH0  64
#define HSW  132            // hs row stride (132 % 32 == 4 -> conflict-free A loads)
#define WBW  136            // wbuf row stride (136 % 32 == 8 -> conflict-free B loads)
#define WBMAT (8 * WBW)     // 1088 floats per matrix chunk
#define WBBUF (2 * WBMAT)   // 2176 floats per buffer

// ---------------- device scratch ----------------
__device__ int   g_len[NSEQ];
__device__ float g_x[NSEQ * SQ * 3];
__device__ float g_h0[(size_t)NSEQ * SQ * CH0];
__device__ float g_bufA[(size_t)NSEQ * SQ * CH];
__device__ float g_bufB[(size_t)NSEQ * SQ * CH];
__device__ float g_skip[(size_t)NSEQ * SQ * CH];
__device__ float g_mean0[NSEQ * CH0];
__device__ float g_mean1[NSEQ * CH];
__device__ float g_cv1T[CH0 * CH];        // cv1_w transposed [k][o] (fp32)
__device__ float g_rwT[3 * CH * CH];      // rs_rw transposed, tf32-rounded
__device__ float g_swT[3 * CH * CH];      // rs_sw transposed, tf32-rounded
__device__ float g_fwR[3 * 384 * CH];     // rs_fw tf32-rounded ([kk][o], native layout)
__device__ float g_gwR[3 * 384 * CH];     // rs_gw tf32-rounded

__device__ __forceinline__ float sigmoidf_(float x) { return 1.f / (1.f + expf(-x)); }

__device__ __forceinline__ float tf32r(float x) {
    unsigned u;
    asm("cvt.rna.tf32.f32 %0, %1;" : "=r"(u) : "f"(x));
    return __uint_as_float(u);
}

__device__ __forceinline__ void cpasync16(unsigned saddr, const void* gptr) {
    asm volatile("cp.async.cg.shared.global [%0], [%1], 16;" :: "r"(saddr), "l"(gptr));
}
__device__ __forceinline__ void cpcommit() { asm volatile("cp.async.commit_group;"); }
__device__ __forceinline__ void cpwait0()  { asm volatile("cp.async.wait_group 0;" ::: "memory"); }

// stage chunk c (8 k-rows x 128 cols per matrix) into padded wbuf[buf]
__device__ __forceinline__ void issue_chunk(unsigned wb0, int buf, int t,
                                            const float* fsrc, const float* gsrc, int c) {
    int kr = t >> 5, c4 = t & 31;
    unsigned off = (unsigned)(buf * WBBUF + kr * WBW + c4 * 4) * 4u;
    cpasync16(wb0 + off,                 (const float4*)(fsrc + c * 1024 + kr * CH) + c4);
    cpasync16(wb0 + off + WBMAT * 4u,    (const float4*)(gsrc + c * 1024 + kr * CH) + c4);
    cpcommit();
}

#define MMA_TF32(C0, C1, C2, C3, A0, A1, A2, A3, B0, B1)                         \
    asm volatile("mma.sync.aligned.m16n8k8.row.col.f32.tf32.tf32.f32 "           \
                 "{%0,%1,%2,%3}, {%4,%5,%6,%7}, {%8,%9}, {%0,%1,%2,%3};"         \
                 : "+f"(C0), "+f"(C1), "+f"(C2), "+f"(C3)                        \
                 : "r"(A0), "r"(A1), "r"(A2), "r"(A3), "r"(B0), "r"(B1))

// ---------------- 1. stable gather per (batch, class) + zero mean buffers ----------------
__global__ void gather_kernel(const float* __restrict__ raw, const int* __restrict__ labels) {
    int seq = blockIdx.x;
    int b = seq / 10, cls = seq % 10 + 1;
    const int* lab = labels + b * SQ;
    __shared__ int cnt[256];
    __shared__ int scan[257];
    int t = threadIdx.x;
    if (t < CH0) g_mean0[seq * CH0 + t] = 0.f;
    if (t < CH)  g_mean1[seq * CH + t]  = 0.f;
    int base = t * 16;
    int c = 0;
#pragma unroll
    for (int u = 0; u < 16; u++) c += (lab[base + u] == cls);
    cnt[t] = c;
    __syncthreads();
    if (t == 0) {
        int acc = 0;
        for (int i = 0; i < 256; i++) { scan[i] = acc; acc += cnt[i]; }
        scan[256] = acc;
        g_len[seq] = acc;
    }
    __syncthreads();
    int w = scan[t];
    const float* xb = raw + (size_t)b * SQ * 3;
    float* dst = g_x + (size_t)seq * SQ * 3;
    for (int u = 0; u < 16; u++) {
        int s = base + u;
        if (lab[s] == cls) {
            dst[w * 3 + 0] = xb[s * 3 + 0];
            dst[w * 3 + 1] = xb[s * 3 + 1];
            dst[w * 3 + 2] = xb[s * 3 + 2];
            w++;
        }
    }
}

// ---------------- prep: transpose + tf32-round weight matrices ----------------
__global__ void prep_kernel(const float* __restrict__ cv1_w,
                            const float* __restrict__ fw, const float* __restrict__ gw,
                            const float* __restrict__ rw, const float* __restrict__ sw) {
    int idx = blockIdx.x * 256 + threadIdx.x;
    if (idx < CH0 * CH) {
        int k = idx / CH, o = idx % CH;
        g_cv1T[idx] = cv1_w[o * CH0 + k];
    }
    if (idx < 3 * CH * CH) {
        int st = idx / (CH * CH);
        int r = idx % (CH * CH);
        int k = r / CH, o = r % CH;
        g_rwT[idx] = tf32r(rw[(size_t)st * CH * CH + o * CH + k]);
        g_swT[idx] = tf32r(sw[(size_t)st * CH * CH + o * CH + k]);
    }
    if (idx < 3 * 384 * CH) {
        g_fwR[idx] = tf32r(fw[idx]);
        g_gwR[idx] = tf32r(gw[idx]);
    }
}

// ---------------- 2. cv0 (K=3), tile-stride loop, fused SE0 mean partial-sums ----------------
__global__ void cv0_kernel(const float* __restrict__ w, const float* __restrict__ b) {
    int seq = blockIdx.y;
    int L = g_len[seq];
    __shared__ float ws[CH0 * 3];
    __shared__ float bs[CH0];
    __shared__ float msum[CH0];
    int t = threadIdx.x;
    if (t < CH0 * 3) ws[t] = w[t];
    if (t < CH0) { bs[t] = b[t]; msum[t] = 0.f; }
    __syncthreads();
    int c0 = (t & 15) * 4;
    for (int j0 = blockIdx.x * 16; j0 < L; j0 += gridDim.x * 16) {
        int j = j0 + (t >> 4);
        if (j < L) {
            const float* xp = g_x + ((size_t)seq * SQ + j) * 3;
            float x0 = xp[0], x1 = xp[1], x2 = xp[2];
            float* out = g_h0 + ((size_t)seq * SQ + j) * CH0;
            float v0 = fmaxf(fmaf(x0, ws[(c0+0)*3+0], fmaf(x1, ws[(c0+0)*3+1], fmaf(x2, ws[(c0+0)*3+2], bs[c0+0]))), 0.f);
            float v1 = fmaxf(fmaf(x0, ws[(c0+1)*3+0], fmaf(x1, ws[(c0+1)*3+1], fmaf(x2, ws[(c0+1)*3+2], bs[c0+1]))), 0.f);
            float v2 = fmaxf(fmaf(x0, ws[(c0+2)*3+0], fmaf(x1, ws[(c0+2)*3+1], fmaf(x2, ws[(c0+2)*3+2], bs[c0+2]))), 0.f);
            float v3 = fmaxf(fmaf(x0, ws[(c0+3)*3+0], fmaf(x1, ws[(c0+3)*3+1], fmaf(x2, ws[(c0+3)*3+2], bs[c0+3]))), 0.f);
            out[c0+0] = v0; out[c0+1] = v1; out[c0+2] = v2; out[c0+3] = v3;
            atomicAdd(&msum[c0+0], v0);
            atomicAdd(&msum[c0+1], v1);
            atomicAdd(&msum[c0+2], v2);
            atomicAdd(&msum[c0+3], v3);
        }
    }
    __syncthreads();
    if (t < CH0 && msum[t] != 0.f) atomicAdd(&g_mean0[seq * CH0 + t], msum[t]);
}

// ---------------- 3. cv1 GEMM, tile-stride loop, SE0 MLP in-block, fused SE1 sums ----------------
__global__ void cv1_kernel(const float* __restrict__ cb,
                           const float* __restrict__ s0w1, const float* __restrict__ s0b1,
                           const float* __restrict__ s0w2, const float* __restrict__ s0b2) {
    int seq = blockIdx.y;
    int L = g_len[seq];
    __shared__ __align__(16) float hs[32 * CH0];
    __shared__ __align__(16) float ws[CH0 * CH];
    __shared__ float sred[8 * CH];
    __shared__ float mn0[CH0];
    __shared__ float hid0[4];
    __shared__ float es0[CH0];
    __shared__ float msum1[CH];
    int t = threadIdx.x;
    float inv = 1.f / fmaxf((float)L, 1.f);
    if (t < CH0) mn0[t] = g_mean0[seq * CH0 + t] * inv;
    if (t < CH) msum1[t] = 0.f;
    __syncthreads();
    if (t < 4) {
        float a = s0b1[t];
        for (int k = 0; k < CH0; k++) a = fmaf(mn0[k], s0w1[t * CH0 + k], a);
        hid0[t] = fmaxf(a, 0.f);
    }
    __syncthreads();
    if (t < CH0) {
        float a = s0b2[t];
#pragma unroll
        for (int h = 0; h < 4; h++) a = fmaf(hid0[h], s0w2[t * 4 + h], a);
        es0[t] = sigmoidf_(a);
    }
    __syncthreads();
    for (int idx = t; idx < CH0 * CH; idx += 256)
        ws[idx] = g_cv1T[idx] * es0[idx >> 7];
    const float* hp = g_h0 + (size_t)seq * SQ * CH0;
    int ty = t >> 5, tx = t & 31;

    for (int j0 = blockIdx.x * 32; j0 < L; j0 += gridDim.x * 32) {
        __syncthreads();
        for (int idx = t; idx < 32 * CH0; idx += 256) {
            int r = idx >> 6;
            int j = j0 + r;
            hs[idx] = (j < L) ? hp[(size_t)j * CH0 + (idx & 63)] : 0.f;
        }
        __syncthreads();
        float acc[16];
#pragma unroll
        for (int i = 0; i < 16; i++) acc[i] = 0.f;
#pragma unroll 4
        for (int k = 0; k < CH0; k++) {
            float a0 = hs[(ty * 4 + 0) * CH0 + k];
            float a1 = hs[(ty * 4 + 1) * CH0 + k];
            float a2 = hs[(ty * 4 + 2) * CH0 + k];
            float a3 = hs[(ty * 4 + 3) * CH0 + k];
            float4 bv = *(const float4*)&ws[k * CH + tx * 4];
            acc[0]  = fmaf(a0, bv.x, acc[0]);  acc[1]  = fmaf(a0, bv.y, acc[1]);
            acc[2]  = fmaf(a0, bv.z, acc[2]);  acc[3]  = fmaf(a0, bv.w, acc[3]);
            acc[4]  = fmaf(a1, bv.x, acc[4]);  acc[5]  = fmaf(a1, bv.y, acc[5]);
            acc[6]  = fmaf(a1, bv.z, acc[6]);  acc[7]  = fmaf(a1, bv.w, acc[7]);
            acc[8]  = fmaf(a2, bv.x, acc[8]);  acc[9]  = fmaf(a2, bv.y, acc[9]);
            acc[10] = fmaf(a2, bv.z, acc[10]); acc[11] = fmaf(a2, bv.w, acc[11]);
            acc[12] = fmaf(a3, bv.x, acc[12]); acc[13] = fmaf(a3, bv.y, acc[13]);
            acc[14] = fmaf(a3, bv.z, acc[14]); acc[15] = fmaf(a3, bv.w, acc[15]);
        }
        float* out = g_bufA + (size_t)seq * SQ * CH;
        float cs0 = 0.f, cs1 = 0.f, cs2 = 0.f, cs3 = 0.f;
#pragma unroll
        for (int p = 0; p < 4; p++) {
            int j = j0 + ty * 4 + p;
            if (j < L) {
                int c = tx * 4;
                float v0 = fmaxf(acc[p * 4 + 0] + cb[c + 0], 0.f);
                float v1 = fmaxf(acc[p * 4 + 1] + cb[c + 1], 0.f);
                float v2 = fmaxf(acc[p * 4 + 2] + cb[c + 2], 0.f);
                float v3 = fmaxf(acc[p * 4 + 3] + cb[c + 3], 0.f);
                out[(size_t)j * CH + c + 0] = v0;
                out[(size_t)j * CH + c + 1] = v1;
                out[(size_t)j * CH + c + 2] = v2;
                out[(size_t)j * CH + c + 3] = v3;
                cs0 += v0; cs1 += v1; cs2 += v2; cs3 += v3;
            }
        }
        sred[ty * CH + tx * 4 + 0] = cs0;
        sred[ty * CH + tx * 4 + 1] = cs1;
        sred[ty * CH + tx * 4 + 2] = cs2;
        sred[ty * CH + tx * 4 + 3] = cs3;
        __syncthreads();
        if (t < CH) {
            float s = 0.f;
#pragma unroll
            for (int w = 0; w < 8; w++) s += sred[w * CH + t];
            msum1[t] += s;
        }
    }
    __syncthreads();
    if (t < CH && msum1[t] != 0.f) atomicAdd(&g_mean1[seq * CH + t], msum1[t]);
}

// ---------------- 4. residual block: tf32 mma.sync, cp.async double buffer ----------------
// 32-row tiles, 8 warps; warp w: rows 16*(w>>2).. +16, cols 32*(w&3).. +32 (4 n-tiles).
__global__ void resblock_kernel(int flip,
                                const float* __restrict__ fb, const float* __restrict__ gb,
                                const float* __restrict__ rb, const float* __restrict__ sb,
                                const float* __restrict__ s1w1, const float* __restrict__ s1b1,
                                const float* __restrict__ s1w2, const float* __restrict__ s1b2,
                                int stack, int skip_init, int applyE, int last) {
    int seq = blockIdx.y;
    int L = g_len[seq];
    int j0 = blockIdx.x * 32;
    if (j0 >= L) return;
    const float* hin = flip ? g_bufB : g_bufA;
    float* hout      = flip ? g_bufA : g_bufB;
    const float* fwp = g_fwR + (size_t)stack * 384 * CH;
    const float* gwp = g_gwR + (size_t)stack * 384 * CH;
    const float* rwT = g_rwT + (size_t)stack * CH * CH;
    const float* swT = g_swT + (size_t)stack * CH * CH;

    __shared__ __align__(16) float hs[34 * HSW];     // rows j0-1..j0+32, stride 132, tf32-rounded
    __shared__ __align__(16) float wbuf[2 * WBBUF];  // 2 bufs x (f,g) x 8x136
    __shared__ float es[CH];
    __shared__ float mn1[CH];
    __shared__ float hid1[8];

    int t = threadIdx.x;
    int lane = t & 31, warp = t >> 5;
    int lr = lane >> 2, lc = lane & 3;
    int mrow0 = (warp >> 2) * 16;
    int ncol0 = (warp & 3) * 32;

    if (applyE) {
        float inv = 1.f / fmaxf((float)L, 1.f);
        if (t < CH) mn1[t] = g_mean1[seq * CH + t] * inv;
        __syncthreads();
        if (t < 8) {
            float a = s1b1[t];
            for (int k = 0; k < CH; k++) a = fmaf(mn1[k], s1w1[t * CH + k], a);
            hid1[t] = fmaxf(a, 0.f);
        }
        __syncthreads();
        if (t < CH) {
            float a = s1b2[t];
#pragma unroll
            for (int h = 0; h < 8; h++) a = fmaf(hid1[h], s1w2[t * 8 + h], a);
            es[t] = sigmoidf_(a);
        }
    } else {
        if (t < CH) es[t] = 1.f;
    }
    __syncthreads();

    const float* hp = hin + (size_t)seq * SQ * CH;
    {
        const float4* e4 = (const float4*)es;
        for (int idx = t; idx < 34 * 32; idx += 256) {
            int r = idx >> 5;
            int c4 = idx & 31;
            int j = j0 - 1 + r;
            float4 v = make_float4(0.f, 0.f, 0.f, 0.f);
            if (j >= 0 && j < L) {
                v = ((const float4*)(hp + (size_t)j * CH))[c4];
                float4 e = e4[c4];
                v.x = tf32r(v.x * e.x); v.y = tf32r(v.y * e.y);
                v.z = tf32r(v.z * e.z); v.w = tf32r(v.w * e.w);
            }
            *(float4*)&hs[r * HSW + c4 * 4] = v;
        }
    }

    unsigned wb0 = (unsigned)__cvta_generic_to_shared(wbuf);

    float cf[16], cg[16];
#pragma unroll
    for (int i = 0; i < 16; i++) { cf[i] = 0.f; cg[i] = 0.f; }

    // ---- phase 1: f/g conv GEMM, K=384 -> 48 k-steps of 8 ----
    issue_chunk(wb0, 0, t, fwp, gwp, 0);
#pragma unroll 1
    for (int c = 0; c < 48; c++) {
        cpwait0();
        __syncthreads();
        if (c < 47) issue_chunk(wb0, (c + 1) & 1, t, fwp, gwp, c + 1);
        const float* wf = wbuf + (c & 1) * WBBUF;
        const float* wg = wf + WBMAT;
        int tap = c >> 4;
        int ck = (c * 8) & 127;
        int ar0 = (mrow0 + lr + tap) * HSW + ck + lc;
        int ar1 = ar0 + 8 * HSW;
        unsigned a0 = __float_as_uint(hs[ar0]);
        unsigned a1 = __float_as_uint(hs[ar1]);
        unsigned a2 = __float_as_uint(hs[ar0 + 4]);
        unsigned a3 = __float_as_uint(hs[ar1 + 4]);
#pragma unroll
        for (int nt = 0; nt < 4; nt++) {
            int n = ncol0 + nt * 8 + lr;
            unsigned bf0 = __float_as_uint(wf[lc * WBW + n]);
            unsigned bf1 = __float_as_uint(wf[(lc + 4) * WBW + n]);
            MMA_TF32(cf[nt*4+0], cf[nt*4+1], cf[nt*4+2], cf[nt*4+3], a0, a1, a2, a3, bf0, bf1);
            unsigned bg0 = __float_as_uint(wg[lc * WBW + n]);
            unsigned bg1 = __float_as_uint(wg[(lc + 4) * WBW + n]);
            MMA_TF32(cg[nt*4+0], cg[nt*4+1], cg[nt*4+2], cg[nt*4+3], a0, a1, a2, a3, bg0, bg1);
        }
    }
    __syncthreads();   // all hs reads complete before zg overwrite

    // ---- gated nonlinearity -> zg tile (tf32-rounded) + prefetch phase-2 chunk 0 ----
    issue_chunk(wb0, 0, t, rwT, swT, 0);
    {
        int m0 = mrow0 + lr, m1 = m0 + 8;
#pragma unroll
        for (int nt = 0; nt < 4; nt++) {
            int col = ncol0 + nt * 8 + 2 * lc;
            float fb0 = fb[col], fb1 = fb[col + 1];
            float gb0 = gb[col], gb1 = gb[col + 1];
            hs[m0 * HSW + col]     = tf32r(tanhf(cf[nt*4+0] + fb0) * sigmoidf_(cg[nt*4+0] + gb0));
            hs[m0 * HSW + col + 1] = tf32r(tanhf(cf[nt*4+1] + fb1) * sigmoidf_(cg[nt*4+1] + gb1));
            hs[m1 * HSW + col]     = tf32r(tanhf(cf[nt*4+2] + fb0) * sigmoidf_(cg[nt*4+2] + gb0));
            hs[m1 * HSW + col + 1] = tf32r(tanhf(cf[nt*4+3] + fb1) * sigmoidf_(cg[nt*4+3] + gb1));
        }
    }
#pragma unroll
    for (int i = 0; i < 16; i++) { cf[i] = 0.f; cg[i] = 0.f; }

    // ---- phase 2: res/skip GEMM, K=128 -> 16 k-steps of 8 ----
#pragma unroll 1
    for (int c = 0; c < 16; c++) {
        cpwait0();
        __syncthreads();   // c==0 also orders zg writes before reads
        if (c < 15) issue_chunk(wb0, (c + 1) & 1, t, rwT, swT, c + 1);
        const float* wf = wbuf + (c & 1) * WBBUF;
        const float* wg = wf + WBMAT;
        int ck = c * 8;
        int ar0 = (mrow0 + lr) * HSW + ck + lc;
        int ar1 = ar0 + 8 * HSW;
        unsigned a0 = __float_as_uint(hs[ar0]);
        unsigned a1 = __float_as_uint(hs[ar1]);
        unsigned a2 = __float_as_uint(hs[ar0 + 4]);
        unsigned a3 = __float_as_uint(hs[ar1 + 4]);
#pragma unroll
        for (int nt = 0; nt < 4; nt++) {
            int n = ncol0 + nt * 8 + lr;
            unsigned br0 = __float_as_uint(wf[lc * WBW + n]);
            unsigned br1 = __float_as_uint(wf[(lc + 4) * WBW + n]);
            MMA_TF32(cf[nt*4+0], cf[nt*4+1], cf[nt*4+2], cf[nt*4+3], a0, a1, a2, a3, br0, br1);
            unsigned bs0 = __float_as_uint(wg[lc * WBW + n]);
            unsigned bs1 = __float_as_uint(wg[(lc + 4) * WBW + n]);
            MMA_TF32(cg[nt*4+0], cg[nt*4+1], cg[nt*4+2], cg[nt*4+3], a0, a1, a2, a3, bs0, bs1);
        }
    }

    // ---- epilogue ----
    float* outr = hout + (size_t)seq * SQ * CH;
    float* outs = g_skip + (size_t)seq * SQ * CH;
    {
        int m0 = mrow0 + lr;
#pragma unroll
        for (int half = 0; half < 2; half++) {
            int m = m0 + half * 8;
            int j = j0 + m;
            if (j < L) {
#pragma unroll
                for (int nt = 0; nt < 4; nt++) {
                    int col = ncol0 + nt * 8 + 2 * lc;
                    float rv0 = cf[nt*4 + half*2 + 0];
                    float rv1 = cf[nt*4 + half*2 + 1];
                    float sv0 = cg[nt*4 + half*2 + 0];
                    float sv1 = cg[nt*4 + half*2 + 1];
                    float2 hv = *(const float2*)(hp + (size_t)j * CH + col);
                    float e0 = es[col], e1 = es[col + 1];
                    float o0 = rv0 + rb[col]     + hv.x * e0;
                    float o1 = rv1 + rb[col + 1] + hv.y * e1;
                    float s0 = sv0 + sb[col];
                    float s1 = sv1 + sb[col + 1];
                    if (!skip_init) {
                        float2 old = *(const float2*)(outs + (size_t)j * CH + col);
                        s0 += old.x; s1 += old.y;
                    }
                    if (last) {
                        float2 w2 = make_float2(o0 + s0, o1 + s1);
                        *(float2*)(outs + (size_t)j * CH + col) = w2;
                    } else {
                        *(float2*)(outr + (size_t)j * CH + col) = make_float2(o0, o1);
                        *(float2*)(outs + (size_t)j * CH + col) = make_float2(s0, s1);
                    }
                }
            }
        }
    }
}

// ---------------- 5. fused masked avg/max pool + head MLP ----------------
__global__ void finalhead_kernel(const float* __restrict__ l1w, const float* __restrict__ l1b,
                                 const float* __restrict__ l2w, const float* __restrict__ l2b,
                                 float* __restrict__ out) {
    int seq = blockIdx.x;
    int L = g_len[seq];
    int t = threadIdx.x;
    __shared__ float ssum[256], smx[256];
    __shared__ float fs[256];
    __shared__ float r0[256], r1[256];
    {
        int c = t & 127, half = t >> 7;
        const float* s = g_skip + (size_t)seq * SQ * CH + c;
        float sum = 0.f, mx = -INFINITY;
        for (int j = half; j < L; j += 2) {
            float v = s[(size_t)j * CH];
            sum += v;
            mx = fmaxf(mx, v);
        }
        ssum[t] = sum; smx[t] = mx;
    }
    __syncthreads();
    if (t < 128) {
        float su = ssum[t] + ssum[t + 128];
        float m = fmaxf(smx[t], smx[t + 128]);
        if (L == 0) m = 0.f;
        float cnt = fmaxf((float)L, 1.f);
        fs[2 * t]     = su / cnt;
        fs[2 * t + 1] = m;
    }
    __syncthreads();
    float o0 = 0.f, o1 = 0.f;
    for (int u = t; u < 1024; u += 256) {
        const float* w = l1w + (size_t)u * 256;
        float a = l1b[u];
#pragma unroll 8
        for (int v = 0; v < 256; v++) a = fmaf(fs[v], w[v], a);
        float hv = fmaxf(a, 0.f);
        o0 = fmaf(hv, l2w[u], o0);
        o1 = fmaf(hv, l2w[1024 + u], o1);
    }
    r0[t] = o0; r1[t] = o1;
    __syncthreads();
    for (int st = 128; st > 0; st >>= 1) {
        if (t < st) { r0[t] += r0[t + st]; r1[t] += r1[t + st]; }
        __syncthreads();
    }
    if (t == 0) {
        out[seq * 2 + 0] = r0[0] + l2b[0];
        out[seq * 2 + 1] = r1[0] + l2b[1];
    }
}

// ---------------- launch ----------------
extern "C" void kernel_launch(void* const* d_in, const int* in_sizes, int n_in,
                              void* d_out, int out_size) {
    const float* raw    = (const float*)d_in[0];
    const int*   labels = (const int*)  d_in[1];
    const float* cv0_w  = (const float*)d_in[2];
    const float* cv0_b  = (const float*)d_in[3];
    const float* se0_w1 = (const float*)d_in[4];
    const float* se0_b1 = (const float*)d_in[5];
    const float* se0_w2 = (const float*)d_in[6];
    const float* se0_b2 = (const float*)d_in[7];
    const float* cv1_w  = (const float*)d_in[8];
    const float* cv1_b  = (const float*)d_in[9];
    const float* se1_w1 = (const float*)d_in[10];
    const float* se1_b1 = (const float*)d_in[11];
    const float* se1_w2 = (const float*)d_in[12];
    const float* se1_b2 = (const float*)d_in[13];
    const float* rs_fw  = (const float*)d_in[14];
    const float* rs_fb  = (const float*)d_in[15];
    const float* rs_gw  = (const float*)d_in[16];
    const float* rs_gb  = (const float*)d_in[17];
    const float* rs_rw  = (const float*)d_in[18];
    const float* rs_rb  = (const float*)d_in[19];
    const float* rs_sw  = (const float*)d_in[20];
    const float* rs_sb  = (const float*)d_in[21];
    const float* l1_w   = (const float*)d_in[22];
    const float* l1_b   = (const float*)d_in[23];
    const float* l2_w   = (const float*)d_in[24];
    const float* l2_b   = (const float*)d_in[25];
    float* out = (float*)d_out;

    gather_kernel<<<NSEQ, 256>>>(raw, labels);
    prep_kernel<<<576, 256>>>(cv1_w, rs_fw, rs_gw, rs_rw, rs_sw);
    cv0_kernel<<<dim3(32, NSEQ), 256>>>(cv0_w, cv0_b);
    cv1_kernel<<<dim3(16, NSEQ), 256>>>(cv1_b, se0_w1, se0_b1, se0_w2, se0_b2);

    for (int st = 0; st < 3; st++) {
        int flip = st & 1;  // 0: A->B, 1: B->A, 2: A->(fused into g_skip)
        resblock_kernel<<<dim3(128, NSEQ), 256>>>(
            flip,
            rs_fb + st * CH, rs_gb + st * CH,
            rs_rb + st * CH, rs_sb + st * CH,
            se1_w1, se1_b1, se1_w2, se1_b2,
            st, st == 0, st == 0, st == 2);
    }
    finalhead_kernel<<<NSEQ, 256>>>(l1_w, l1_b, l2_w, l2_b, out);
}

// round 16
// speedup vs baseline: 1.7964x; 1.0458x over previous
#include <cuda_runtime.h>
#include <cstdint>
#include <math.h>

#define SQ   4096
#define NSEQ 80
#define CH   128
#define CH0  64
#define HSW  132              // hs row stride (conflict-free A loads)
#define WBW  136              // wbuf row stride (conflict-free B loads)
#define WBMAT16 (16 * WBW)    // 2176 floats per matrix chunk (16 k-rows)
#define WBBUF16 (2 * WBMAT16) // per buffer (f+g)

// ---------------- device scratch ----------------
__device__ int   g_len[NSEQ];
__device__ float g_x[NSEQ * SQ * 3];
__device__ float g_h0[(size_t)NSEQ * SQ * CH0];
__device__ float g_bufA[(size_t)NSEQ * SQ * CH];
__device__ float g_bufB[(size_t)NSEQ * SQ * CH];
__device__ float g_skip[(size_t)NSEQ * SQ * CH];
__device__ float g_mean0[NSEQ * CH0];
__device__ float g_mean1[NSEQ * CH];
__device__ float g_cv1T[CH0 * CH];        // cv1_w transposed [k][o] (fp32)
__device__ float g_rwT[3 * CH * CH];      // rs_rw transposed, tf32-rounded
__device__ float g_swT[3 * CH * CH];      // rs_sw transposed, tf32-rounded
__device__ float g_fwR[3 * 384 * CH];     // rs_fw tf32-rounded
__device__ float g_gwR[3 * 384 * CH];     // rs_gw tf32-rounded

__device__ __forceinline__ float sigmoidf_(float x) { return 1.f / (1.f + expf(-x)); }

__device__ __forceinline__ float tf32r(float x) {
    unsigned u;
    asm("cvt.rna.tf32.f32 %0, %1;" : "=r"(u) : "f"(x));
    return __uint_as_float(u);
}

__device__ __forceinline__ void cpasync16(unsigned saddr, const void* gptr) {
    asm volatile("cp.async.cg.shared.global [%0], [%1], 16;" :: "r"(saddr), "l"(gptr));
}
__device__ __forceinline__ void cpcommit() { asm volatile("cp.async.commit_group;"); }
__device__ __forceinline__ void cpwait0()  { asm volatile("cp.async.wait_group 0;" ::: "memory"); }

// stage chunk c (16 k-rows x 128 cols per matrix) into padded wbuf[buf]
__device__ __forceinline__ void issue_chunk16(unsigned wb0, int buf, int t,
                                              const float* fsrc, const float* gsrc, int c) {
#pragma unroll
    for (int u = 0; u < 2; u++) {
        int idx = t + u * 256;          // 512 float4 per matrix
        int kr = idx >> 5, c4 = idx & 31;
        unsigned off = (unsigned)(buf * WBBUF16 + kr * WBW + c4 * 4) * 4u;
        cpasync16(wb0 + off,                  (const float4*)(fsrc + (c * 16 + kr) * CH) + c4);
        cpasync16(wb0 + off + WBMAT16 * 4u,   (const float4*)(gsrc + (c * 16 + kr) * CH) + c4);
    }
    cpcommit();
}

#define MMA_TF32(C0, C1, C2, C3, A0, A1, A2, A3, B0, B1)                         \
    asm volatile("mma.sync.aligned.m16n8k8.row.col.f32.tf32.tf32.f32 "           \
                 "{%0,%1,%2,%3}, {%4,%5,%6,%7}, {%8,%9}, {%0,%1,%2,%3};"         \
                 : "+f"(C0), "+f"(C1), "+f"(C2), "+f"(C3)                        \
                 : "r"(A0), "r"(A1), "r"(A2), "r"(A3), "r"(B0), "r"(B1))

// ---------------- 1. stable gather per (batch, class) + zero mean buffers ----------------
__global__ void gather_kernel(const float* __restrict__ raw, const int* __restrict__ labels) {
    int seq = blockIdx.x;
    int b = seq / 10, cls = seq % 10 + 1;
    const int* lab = labels + b * SQ;
    __shared__ int cnt[256];
    __shared__ int scan[257];
    int t = threadIdx.x;
    if (t < CH0) g_mean0[seq * CH0 + t] = 0.f;
    if (t < CH)  g_mean1[seq * CH + t]  = 0.f;
    int base = t * 16;
    int c = 0;
#pragma unroll
    for (int u = 0; u < 16; u++) c += (lab[base + u] == cls);
    cnt[t] = c;
    __syncthreads();
    if (t == 0) {
        int acc = 0;
        for (int i = 0; i < 256; i++) { scan[i] = acc; acc += cnt[i]; }
        scan[256] = acc;
        g_len[seq] = acc;
    }
    __syncthreads();
    int w = scan[t];
    const float* xb = raw + (size_t)b * SQ * 3;
    float* dst = g_x + (size_t)seq * SQ * 3;
    for (int u = 0; u < 16; u++) {
        int s = base + u;
        if (lab[s] == cls) {
            dst[w * 3 + 0] = xb[s * 3 + 0];
            dst[w * 3 + 1] = xb[s * 3 + 1];
            dst[w * 3 + 2] = xb[s * 3 + 2];
            w++;
        }
    }
}

// ---------------- prep: transpose + tf32-round weight matrices ----------------
__global__ void prep_kernel(const float* __restrict__ cv1_w,
                            const float* __restrict__ fw, const float* __restrict__ gw,
                            const float* __restrict__ rw, const float* __restrict__ sw) {
    int idx = blockIdx.x * 256 + threadIdx.x;
    if (idx < CH0 * CH) {
        int k = idx / CH, o = idx % CH;
        g_cv1T[idx] = cv1_w[o * CH0 + k];
    }
    if (idx < 3 * CH * CH) {
        int st = idx / (CH * CH);
        int r = idx % (CH * CH);
        int k = r / CH, o = r % CH;
        g_rwT[idx] = tf32r(rw[(size_t)st * CH * CH + o * CH + k]);
        g_swT[idx] = tf32r(sw[(size_t)st * CH * CH + o * CH + k]);
    }
    if (idx < 3 * 384 * CH) {
        g_fwR[idx] = tf32r(fw[idx]);
        g_gwR[idx] = tf32r(gw[idx]);
    }
}

// ---------------- 2. cv0 (K=3), tile-stride loop, fused SE0 mean partial-sums ----------------
__global__ void cv0_kernel(const float* __restrict__ w, const float* __restrict__ b) {
    int seq = blockIdx.y;
    int L = g_len[seq];
    __shared__ float ws[CH0 * 3];
    __shared__ float bs[CH0];
    __shared__ float msum[CH0];
    int t = threadIdx.x;
    if (t < CH0 * 3) ws[t] = w[t];
    if (t < CH0) { bs[t] = b[t]; msum[t] = 0.f; }
    __syncthreads();
    int c0 = (t & 15) * 4;
    for (int j0 = blockIdx.x * 16; j0 < L; j0 += gridDim.x * 16) {
        int j = j0 + (t >> 4);
        if (j < L) {
            const float* xp = g_x + ((size_t)seq * SQ + j) * 3;
            float x0 = xp[0], x1 = xp[1], x2 = xp[2];
            float* out = g_h0 + ((size_t)seq * SQ + j) * CH0;
            float v0 = fmaxf(fmaf(x0, ws[(c0+0)*3+0], fmaf(x1, ws[(c0+0)*3+1], fmaf(x2, ws[(c0+0)*3+2], bs[c0+0]))), 0.f);
            float v1 = fmaxf(fmaf(x0, ws[(c0+1)*3+0], fmaf(x1, ws[(c0+1)*3+1], fmaf(x2, ws[(c0+1)*3+2], bs[c0+1]))), 0.f);
            float v2 = fmaxf(fmaf(x0, ws[(c0+2)*3+0], fmaf(x1, ws[(c0+2)*3+1], fmaf(x2, ws[(c0+2)*3+2], bs[c0+2]))), 0.f);
            float v3 = fmaxf(fmaf(x0, ws[(c0+3)*3+0], fmaf(x1, ws[(c0+3)*3+1], fmaf(x2, ws[(c0+3)*3+2], bs[c0+3]))), 0.f);
            out[c0+0] = v0; out[c0+1] = v1; out[c0+2] = v2; out[c0+3] = v3;
            atomicAdd(&msum[c0+0], v0);
            atomicAdd(&msum[c0+1], v1);
            atomicAdd(&msum[c0+2], v2);
            atomicAdd(&msum[c0+3], v3);
        }
    }
    __syncthreads();
    if (t < CH0 && msum[t] != 0.f) atomicAdd(&g_mean0[seq * CH0 + t], msum[t]);
}

// ---------------- 3. cv1 GEMM, tile-stride loop, SE0 MLP in-block, fused SE1 sums ----------------
__global__ void cv1_kernel(const float* __restrict__ cb,
                           const float* __restrict__ s0w1, const float* __restrict__ s0b1,
                           const float* __restrict__ s0w2, const float* __restrict__ s0b2) {
    int seq = blockIdx.y;
    int L = g_len[seq];
    __shared__ __align__(16) float hs[32 * CH0];
    __shared__ __align__(16) float ws[CH0 * CH];
    __shared__ float sred[8 * CH];
    __shared__ float mn0[CH0];
    __shared__ float hid0[4];
    __shared__ float es0[CH0];
    __shared__ float msum1[CH];
    int t = threadIdx.x;
    float inv = 1.f / fmaxf((float)L, 1.f);
    if (t < CH0) mn0[t] = g_mean0[seq * CH0 + t] * inv;
    if (t < CH) msum1[t] = 0.f;
    __syncthreads();
    if (t < 4) {
        float a = s0b1[t];
        for (int k = 0; k < CH0; k++) a = fmaf(mn0[k], s0w1[t * CH0 + k], a);
        hid0[t] = fmaxf(a, 0.f);
    }
    __syncthreads();
    if (t < CH0) {
        float a = s0b2[t];
#pragma unroll
        for (int h = 0; h < 4; h++) a = fmaf(hid0[h], s0w2[t * 4 + h], a);
        es0[t] = sigmoidf_(a);
    }
    __syncthreads();
    for (int idx = t; idx < CH0 * CH; idx += 256)
        ws[idx] = g_cv1T[idx] * es0[idx >> 7];
    const float* hp = g_h0 + (size_t)seq * SQ * CH0;
    int ty = t >> 5, tx = t & 31;

    for (int j0 = blockIdx.x * 32; j0 < L; j0 += gridDim.x * 32) {
        __syncthreads();
        for (int idx = t; idx < 32 * CH0; idx += 256) {
            int r = idx >> 6;
            int j = j0 + r;
            hs[idx] = (j < L) ? hp[(size_t)j * CH0 + (idx & 63)] : 0.f;
        }
        __syncthreads();
        float acc[16];
#pragma unroll
        for (int i = 0; i < 16; i++) acc[i] = 0.f;
#pragma unroll 4
        for (int k = 0; k < CH0; k++) {
            float a0 = hs[(ty * 4 + 0) * CH0 + k];
            float a1 = hs[(ty * 4 + 1) * CH0 + k];
            float a2 = hs[(ty * 4 + 2) * CH0 + k];
            float a3 = hs[(ty * 4 + 3) * CH0 + k];
            float4 bv = *(const float4*)&ws[k * CH + tx * 4];
            acc[0]  = fmaf(a0, bv.x, acc[0]);  acc[1]  = fmaf(a0, bv.y, acc[1]);
            acc[2]  = fmaf(a0, bv.z, acc[2]);  acc[3]  = fmaf(a0, bv.w, acc[3]);
            acc[4]  = fmaf(a1, bv.x, acc[4]);  acc[5]  = fmaf(a1, bv.y, acc[5]);
            acc[6]  = fmaf(a1, bv.z, acc[6]);  acc[7]  = fmaf(a1, bv.w, acc[7]);
            acc[8]  = fmaf(a2, bv.x, acc[8]);  acc[9]  = fmaf(a2, bv.y, acc[9]);
            acc[10] = fmaf(a2, bv.z, acc[10]); acc[11] = fmaf(a2, bv.w, acc[11]);
            acc[12] = fmaf(a3, bv.x, acc[12]); acc[13] = fmaf(a3, bv.y, acc[13]);
            acc[14] = fmaf(a3, bv.z, acc[14]); acc[15] = fmaf(a3, bv.w, acc[15]);
        }
        float* out = g_bufA + (size_t)seq * SQ * CH;
        float cs0 = 0.f, cs1 = 0.f, cs2 = 0.f, cs3 = 0.f;
#pragma unroll
        for (int p = 0; p < 4; p++) {
            int j = j0 + ty * 4 + p;
            if (j < L) {
                int c = tx * 4;
                float v0 = fmaxf(acc[p * 4 + 0] + cb[c + 0], 0.f);
                float v1 = fmaxf(acc[p * 4 + 1] + cb[c + 1], 0.f);
                float v2 = fmaxf(acc[p * 4 + 2] + cb[c + 2], 0.f);
                float v3 = fmaxf(acc[p * 4 + 3] + cb[c + 3], 0.f);
                out[(size_t)j * CH + c + 0] = v0;
                out[(size_t)j * CH + c + 1] = v1;
                out[(size_t)j * CH + c + 2] = v2;
                out[(size_t)j * CH + c + 3] = v3;
                cs0 += v0; cs1 += v1; cs2 += v2; cs3 += v3;
            }
        }
        sred[ty * CH + tx * 4 + 0] = cs0;
        sred[ty * CH + tx * 4 + 1] = cs1;
        sred[ty * CH + tx * 4 + 2] = cs2;
        sred[ty * CH + tx * 4 + 3] = cs3;
        __syncthreads();
        if (t < CH) {
            float s = 0.f;
#pragma unroll
            for (int w = 0; w < 8; w++) s += sred[w * CH + t];
            msum1[t] += s;
        }
    }
    __syncthreads();
    if (t < CH && msum1[t] != 0.f) atomicAdd(&g_mean1[seq * CH + t], msum1[t]);
}

// ---------------- 4. residual block: tf32 mma.sync, 16-k chunks, cp.async double buffer ----
// 32-row tiles, 8 warps; warp w: rows 16*(w>>2)..+16, cols 32*(w&3)..+32.
__global__ void resblock_kernel(int flip,
                                const float* __restrict__ fb, const float* __restrict__ gb,
                                const float* __restrict__ rb, const float* __restrict__ sb,
                                const float* __restrict__ s1w1, const float* __restrict__ s1b1,
                                const float* __restrict__ s1w2, const float* __restrict__ s1b2,
                                int stack, int skip_init, int applyE, int last) {
    int seq = blockIdx.y;
    int L = g_len[seq];
    int j0 = blockIdx.x * 32;
    if (j0 >= L) return;
    const float* hin = flip ? g_bufB : g_bufA;
    float* hout      = flip ? g_bufA : g_bufB;
    const float* fwp = g_fwR + (size_t)stack * 384 * CH;
    const float* gwp = g_gwR + (size_t)stack * 384 * CH;
    const float* rwT = g_rwT + (size_t)stack * CH * CH;
    const float* swT = g_swT + (size_t)stack * CH * CH;

    extern __shared__ __align__(16) float sm[];
    float* hs   = sm;                    // 34 * HSW floats
    float* wbuf = sm + 34 * HSW;         // 2 * WBBUF16 floats
    __shared__ float es[CH];
    __shared__ float mn1[CH];
    __shared__ float hid1[8];

    int t = threadIdx.x;
    int lane = t & 31, warp = t >> 5;
    int lr = lane >> 2, lc = lane & 3;
    int mrow0 = (warp >> 2) * 16;
    int ncol0 = (warp & 3) * 32;

    if (applyE) {
        float inv = 1.f / fmaxf((float)L, 1.f);
        if (t < CH) mn1[t] = g_mean1[seq * CH + t] * inv;
        __syncthreads();
        if (t < 8) {
            float a = s1b1[t];
            for (int k = 0; k < CH; k++) a = fmaf(mn1[k], s1w1[t * CH + k], a);
            hid1[t] = fmaxf(a, 0.f);
        }
        __syncthreads();
        if (t < CH) {
            float a = s1b2[t];
#pragma unroll
            for (int h = 0; h < 8; h++) a = fmaf(hid1[h], s1w2[t * 8 + h], a);
            es[t] = sigmoidf_(a);
        }
    } else {
        if (t < CH) es[t] = 1.f;
    }
    __syncthreads();

    const float* hp = hin + (size_t)seq * SQ * CH;
    {
        const float4* e4 = (const float4*)es;
        for (int idx = t; idx < 34 * 32; idx += 256) {
            int r = idx >> 5;
            int c4 = idx & 31;
            int j = j0 - 1 + r;
            float4 v = make_float4(0.f, 0.f, 0.f, 0.f);
            if (j >= 0 && j < L) {
                v = ((const float4*)(hp + (size_t)j * CH))[c4];
                float4 e = e4[c4];
                v.x = tf32r(v.x * e.x); v.y = tf32r(v.y * e.y);
                v.z = tf32r(v.z * e.z); v.w = tf32r(v.w * e.w);
            }
            *(float4*)&hs[r * HSW + c4 * 4] = v;
        }
    }

    unsigned wb0 = (unsigned)__cvta_generic_to_shared(wbuf);

    float cf[16], cg[16];
#pragma unroll
    for (int i = 0; i < 16; i++) { cf[i] = 0.f; cg[i] = 0.f; }

    // ---- phase 1: f/g conv GEMM, K=384 -> 24 chunks of 16 ----
    issue_chunk16(wb0, 0, t, fwp, gwp, 0);
#pragma unroll 1
    for (int c = 0; c < 24; c++) {
        cpwait0();
        __syncthreads();
        if (c < 23) issue_chunk16(wb0, (c + 1) & 1, t, fwp, gwp, c + 1);
        const float* wf = wbuf + (c & 1) * WBBUF16;
        const float* wg = wf + WBMAT16;
        int tap = c >> 3;
#pragma unroll
        for (int ks = 0; ks < 2; ks++) {
            int ck = (c * 16 + ks * 8) & 127;
            int ar0 = (mrow0 + lr + tap) * HSW + ck + lc;
            int ar1 = ar0 + 8 * HSW;
            unsigned a0 = __float_as_uint(hs[ar0]);
            unsigned a1 = __float_as_uint(hs[ar1]);
            unsigned a2 = __float_as_uint(hs[ar0 + 4]);
            unsigned a3 = __float_as_uint(hs[ar1 + 4]);
            int krb = ks * 8;
#pragma unroll
            for (int nt = 0; nt < 4; nt++) {
                int n = ncol0 + nt * 8 + lr;
                unsigned bf0 = __float_as_uint(wf[(krb + lc) * WBW + n]);
                unsigned bf1 = __float_as_uint(wf[(krb + lc + 4) * WBW + n]);
                MMA_TF32(cf[nt*4+0], cf[nt*4+1], cf[nt*4+2], cf[nt*4+3], a0, a1, a2, a3, bf0, bf1);
                unsigned bg0 = __float_as_uint(wg[(krb + lc) * WBW + n]);
                unsigned bg1 = __float_as_uint(wg[(krb + lc + 4) * WBW + n]);
                MMA_TF32(cg[nt*4+0], cg[nt*4+1], cg[nt*4+2], cg[nt*4+3], a0, a1, a2, a3, bg0, bg1);
            }
        }
    }
    __syncthreads();   // all hs reads complete before zg overwrite

    // ---- gated nonlinearity -> zg tile + prefetch phase-2 chunk 0 ----
    issue_chunk16(wb0, 0, t, rwT, swT, 0);
    {
        int m0 = mrow0 + lr, m1 = m0 + 8;
#pragma unroll
        for (int nt = 0; nt < 4; nt++) {
            int col = ncol0 + nt * 8 + 2 * lc;
            float fb0 = fb[col], fb1 = fb[col + 1];
            float gb0 = gb[col], gb1 = gb[col + 1];
            hs[m0 * HSW + col]     = tf32r(tanhf(cf[nt*4+0] + fb0) * sigmoidf_(cg[nt*4+0] + gb0));
            hs[m0 * HSW + col + 1] = tf32r(tanhf(cf[nt*4+1] + fb1) * sigmoidf_(cg[nt*4+1] + gb1));
            hs[m1 * HSW + col]     = tf32r(tanhf(cf[nt*4+2] + fb0) * sigmoidf_(cg[nt*4+2] + gb0));
            hs[m1 * HSW + col + 1] = tf32r(tanhf(cf[nt*4+3] + fb1) * sigmoidf_(cg[nt*4+3] + gb1));
        }
    }
#pragma unroll
    for (int i = 0; i < 16; i++) { cf[i] = 0.f; cg[i] = 0.f; }

    // ---- phase 2: res/skip GEMM, K=128 -> 8 chunks of 16 ----
#pragma unroll 1
    for (int c = 0; c < 8; c++) {
        cpwait0();
        __syncthreads();   // c==0 also orders zg writes before reads
        if (c < 7) issue_chunk16(wb0, (c + 1) & 1, t, rwT, swT, c + 1);
        const float* wf = wbuf + (c & 1) * WBBUF16;
        const float* wg = wf + WBMAT16;
#pragma unroll
        for (int ks = 0; ks < 2; ks++) {
            int ck = c * 16 + ks * 8;
            int ar0 = (mrow0 + lr) * HSW + ck + lc;
            int ar1 = ar0 + 8 * HSW;
            unsigned a0 = __float_as_uint(hs[ar0]);
            unsigned a1 = __float_as_uint(hs[ar1]);
            unsigned a2 = __float_as_uint(hs[ar0 + 4]);
            unsigned a3 = __float_as_uint(hs[ar1 + 4]);
            int krb = ks * 8;
#pragma unroll
            for (int nt = 0; nt < 4; nt++) {
                int n = ncol0 + nt * 8 + lr;
                unsigned br0 = __float_as_uint(wf[(krb + lc) * WBW + n]);
                unsigned br1 = __float_as_uint(wf[(krb + lc + 4) * WBW + n]);
                MMA_TF32(cf[nt*4+0], cf[nt*4+1], cf[nt*4+2], cf[nt*4+3], a0, a1, a2, a3, br0, br1);
                unsigned bs0 = __float_as_uint(wg[(krb + lc) * WBW + n]);
                unsigned bs1 = __float_as_uint(wg[(krb + lc + 4) * WBW + n]);
                MMA_TF32(cg[nt*4+0], cg[nt*4+1], cg[nt*4+2], cg[nt*4+3], a0, a1, a2, a3, bs0, bs1);
            }
        }
    }

    // ---- epilogue ----
    float* outr = hout + (size_t)seq * SQ * CH;
    float* outs = g_skip + (size_t)seq * SQ * CH;
    {
        int m0 = mrow0 + lr;
#pragma unroll
        for (int half = 0; half < 2; half++) {
            int m = m0 + half * 8;
            int j = j0 + m;
            if (j < L) {
#pragma unroll
                for (int nt = 0; nt < 4; nt++) {
                    int col = ncol0 + nt * 8 + 2 * lc;
                    float rv0 = cf[nt*4 + half*2 + 0];
                    float rv1 = cf[nt*4 + half*2 + 1];
                    float sv0 = cg[nt*4 + half*2 + 0];
                    float sv1 = cg[nt*4 + half*2 + 1];
                    float2 hv = *(const float2*)(hp + (size_t)j * CH + col);
                    float e0 = es[col], e1 = es[col + 1];
                    float o0 = rv0 + rb[col]     + hv.x * e0;
                    float o1 = rv1 + rb[col + 1] + hv.y * e1;
                    float s0 = sv0 + sb[col];
                    float s1 = sv1 + sb[col + 1];
                    if (!skip_init) {
                        float2 old = *(const float2*)(outs + (size_t)j * CH + col);
                        s0 += old.x; s1 += old.y;
                    }
                    if (last) {
                        *(float2*)(outs + (size_t)j * CH + col) = make_float2(o0 + s0, o1 + s1);
                    } else {
                        *(float2*)(outr + (size_t)j * CH + col) = make_float2(o0, o1);
                        *(float2*)(outs + (size_t)j * CH + col) = make_float2(s0, s1);
                    }
                }
            }
        }
    }
}

// ---------------- 5. fused masked avg/max pool + head MLP ----------------
__global__ void finalhead_kernel(const float* __restrict__ l1w, const float* __restrict__ l1b,
                                 const float* __restrict__ l2w, const float* __restrict__ l2b,
                                 float* __restrict__ out) {
    int seq = blockIdx.x;
    int L = g_len[seq];
    int t = threadIdx.x;
    __shared__ float ssum[256], smx[256];
    __shared__ float fs[256];
    __shared__ float r0[256], r1[256];
    {
        int c = t & 127, half = t >> 7;
        const float* s = g_skip + (size_t)seq * SQ * CH + c;
        float sum = 0.f, mx = -INFINITY;
        for (int j = half; j < L; j += 2) {
            float v = s[(size_t)j * CH];
            sum += v;
            mx = fmaxf(mx, v);
        }
        ssum[t] = sum; smx[t] = mx;
    }
    __syncthreads();
    if (t < 128) {
        float su = ssum[t] + ssum[t + 128];
        float m = fmaxf(smx[t], smx[t + 128]);
        if (L == 0) m = 0.f;
        float cnt = fmaxf((float)L, 1.f);
        fs[2 * t]     = su / cnt;
        fs[2 * t + 1] = m;
    }
    __syncthreads();
    float o0 = 0.f, o1 = 0.f;
    for (int u = t; u < 1024; u += 256) {
        const float* w = l1w + (size_t)u * 256;
        float a = l1b[u];
#pragma unroll 8
        for (int v = 0; v < 256; v++) a = fmaf(fs[v], w[v], a);
        float hv = fmaxf(a, 0.f);
        o0 = fmaf(hv, l2w[u], o0);
        o1 = fmaf(hv, l2w[1024 + u], o1);
    }
    r0[t] = o0; r1[t] = o1;
    __syncthreads();
    for (int st = 128; st > 0; st >>= 1) {
        if (t < st) { r0[t] += r0[t + st]; r1[t] += r1[t + st]; }
        __syncthreads();
    }
    if (t == 0) {
        out[seq * 2 + 0] = r0[0] + l2b[0];
        out[seq * 2 + 1] = r1[0] + l2b[1];
    }
}

// ---------------- launch ----------------
extern "C" void kernel_launch(void* const* d_in, const int* in_sizes, int n_in,
                              void* d_out, int out_size) {
    const float* raw    = (const float*)d_in[0];
    const int*   labels = (const int*)  d_in[1];
    const float* cv0_w  = (const float*)d_in[2];
    const float* cv0_b  = (const float*)d_in[3];
    const float* se0_w1 = (const float*)d_in[4];
    const float* se0_b1 = (const float*)d_in[5];
    const float* se0_w2 = (const float*)d_in[6];
    const float* se0_b2 = (const float*)d_in[7];
    const float* cv1_w  = (const float*)d_in[8];
    const float* cv1_b  = (const float*)d_in[9];
    const float* se1_w1 = (const float*)d_in[10];
    const float* se1_b1 = (const float*)d_in[11];
    const float* se1_w2 = (const float*)d_in[12];
    const float* se1_b2 = (const float*)d_in[13];
    const float* rs_fw  = (const float*)d_in[14];
    const float* rs_fb  = (const float*)d_in[15];
    const float* rs_gw  = (const float*)d_in[16];
    const float* rs_gb  = (const float*)d_in[17];
    const float* rs_rw  = (const float*)d_in[18];
    const float* rs_rb  = (const float*)d_in[19];
    const float* rs_sw  = (const float*)d_in[20];
    const float* rs_sb  = (const float*)d_in[21];
    const float* l1_w   = (const float*)d_in[22];
    const float* l1_b   = (const float*)d_in[23];
    const float* l2_w   = (const float*)d_in[24];
    const float* l2_b   = (const float*)d_in[25];
    float* out = (float*)d_out;

    const int RES_SMEM = (34 * HSW + 2 * WBBUF16) * 4;   // 52768 B
    cudaFuncSetAttribute(resblock_kernel,
                         cudaFuncAttributeMaxDynamicSharedMemorySize, RES_SMEM);

    gather_kernel<<<NSEQ, 256>>>(raw, labels);
    prep_kernel<<<576, 256>>>(cv1_w, rs_fw, rs_gw, rs_rw, rs_sw);
    cv0_kernel<<<dim3(32, NSEQ), 256>>>(cv0_w, cv0_b);
    cv1_kernel<<<dim3(16, NSEQ), 256>>>(cv1_b, se0_w1, se0_b1, se0_w2, se0_b2);

    for (int st = 0; st < 3; st++) {
        int flip = st & 1;  // 0: A->B, 1: B->A, 2: A->(fused into g_skip)
        resblock_kernel<<<dim3(128, NSEQ), 256, RES_SMEM>>>(
            flip,
            rs_fb + st * CH, rs_gb + st * CH,
            rs_rb + st * CH, rs_sb + st * CH,
            se1_w1, se1_b1, se1_w2, se1_b2,
            st, st == 0, st == 0, st == 2);
    }
    finalhead_kernel<<<NSEQ, 256>>>(l1_w, l1_b, l2_w, l2_b, out);
}